// round 3
// baseline (speedup 1.0000x reference)
#include <cuda_runtime.h>
#include <cstdint>
#include <cstddef>

// ---------------------------------------------------------------------------
// RelativeAttention: out = softmax(quant(l2n(xWq) @ l2n(aWk)^T)) @ values
// B=16384, A=4096, D=H=512, fp32 throughout (quantization makes tf32 unsafe).
//
// Pipeline:
//   1) g_Q  = x @ Wq            (SGEMM, EPI_STORE)
//   2) g_Kn = anchors @ Wk      (SGEMM, EPI_STORE)
//   3) l2-normalize rows of g_Q and g_Kn
//   4) zero g_den
//   5) g_E  = exp(round((g_Q@g_Kn^T)/0.05)*0.05); g_den += rowsum (EPI_SIM)
//   6) out  = (g_E @ values) / g_den                              (EPI_OUT)
// ---------------------------------------------------------------------------

#define BM 128
#define BN 128
#define BK 8

// Scratch (device globals: allocation-free per harness rules)
__device__ float g_Q[16384 * 512];
__device__ float g_Kn[4096 * 512];
__device__ float g_E[(size_t)16384 * 4096];
__device__ float g_den[16384];

enum { EPI_STORE = 0, EPI_SIM = 1, EPI_OUT = 2 };

// C[M,N] = A[M,K] @ op(B);  BT=true: B is [N,K] row-major (use B^T), else [K,N].
// 256 threads, 128x128 tile, 8x8 per thread, double-buffered smem, K%8==0,
// all dims multiples of tile sizes (true for this problem).
template <bool BT, int EPI>
__global__ __launch_bounds__(256, 2) void gemm_kernel(
    const float* __restrict__ A, const float* __restrict__ Bm,
    float* __restrict__ C, int M, int N, int K, float* __restrict__ den)
{
    __shared__ float As[2][BK][BM];
    __shared__ float Bs[2][BK][BN];

    const int tid = threadIdx.x;
    const int tx = tid & 15;          // 0..15 -> N direction
    const int ty = tid >> 4;          // 0..15 -> M direction
    const int bm0 = blockIdx.y * BM;
    const int bn0 = blockIdx.x * BN;

    // A tile loader: 128 rows x 8 cols, float4 per thread, transposed store
    const int ar = tid >> 1;          // 0..127
    const int ac = (tid & 1) * 4;     // 0 or 4
    const float* Ap = A + (size_t)(bm0 + ar) * K + ac;

    // B tile loader
    int br, bc;
    const float* Bp;
    if constexpr (BT) {
        br = tid >> 1; bc = (tid & 1) * 4;          // like A
        Bp = Bm + (size_t)(bn0 + br) * K + bc;
    } else {
        br = tid >> 5; bc = (tid & 31) * 4;         // 8 rows x 128 cols
        Bp = Bm + (size_t)br * N + bn0 + bc;
    }

    float acc[8][8];
#pragma unroll
    for (int i = 0; i < 8; i++)
#pragma unroll
        for (int j = 0; j < 8; j++) acc[i][j] = 0.f;

    // preload tile 0 into smem buffer 0
    {
        float4 pa = *(const float4*)Ap;
        As[0][ac + 0][ar] = pa.x;
        As[0][ac + 1][ar] = pa.y;
        As[0][ac + 2][ar] = pa.z;
        As[0][ac + 3][ar] = pa.w;
        if constexpr (BT) {
            float4 pb = *(const float4*)Bp;
            Bs[0][bc + 0][br] = pb.x;
            Bs[0][bc + 1][br] = pb.y;
            Bs[0][bc + 2][br] = pb.z;
            Bs[0][bc + 3][br] = pb.w;
        } else {
            *(float4*)&Bs[0][br][bc] = *(const float4*)Bp;
        }
    }
    __syncthreads();

    const int nk = K / BK;
    int buf = 0;
    for (int t = 0; t < nk; t++) {
        float4 na, nb;
        const bool has = (t + 1 < nk);
        if (has) {
            const int ko = (t + 1) * BK;
            na = *(const float4*)(Ap + ko);
            if constexpr (BT) nb = *(const float4*)(Bp + ko);
            else              nb = *(const float4*)(Bp + (size_t)ko * N);
        }
#pragma unroll
        for (int kk = 0; kk < BK; kk++) {
            float ra[8], rb[8];
            *(float4*)&ra[0] = *(const float4*)&As[buf][kk][ty * 8];
            *(float4*)&ra[4] = *(const float4*)&As[buf][kk][ty * 8 + 4];
            *(float4*)&rb[0] = *(const float4*)&Bs[buf][kk][tx * 8];
            *(float4*)&rb[4] = *(const float4*)&Bs[buf][kk][tx * 8 + 4];
#pragma unroll
            for (int i = 0; i < 8; i++)
#pragma unroll
                for (int j = 0; j < 8; j++)
                    acc[i][j] = fmaf(ra[i], rb[j], acc[i][j]);
        }
        if (has) {
            buf ^= 1;
            As[buf][ac + 0][ar] = na.x;
            As[buf][ac + 1][ar] = na.y;
            As[buf][ac + 2][ar] = na.z;
            As[buf][ac + 3][ar] = na.w;
            if constexpr (BT) {
                Bs[buf][bc + 0][br] = nb.x;
                Bs[buf][bc + 1][br] = nb.y;
                Bs[buf][bc + 2][br] = nb.z;
                Bs[buf][bc + 3][br] = nb.w;
            } else {
                *(float4*)&Bs[buf][br][bc] = nb;
            }
            __syncthreads();
        }
    }

    const int m0 = bm0 + ty * 8;
    const int n0 = bn0 + tx * 8;

    if constexpr (EPI == EPI_STORE) {
#pragma unroll
        for (int i = 0; i < 8; i++) {
            *(float4*)&C[(size_t)(m0 + i) * N + n0]     = *(float4*)&acc[i][0];
            *(float4*)&C[(size_t)(m0 + i) * N + n0 + 4] = *(float4*)&acc[i][4];
        }
    } else if constexpr (EPI == EPI_SIM) {
#pragma unroll
        for (int i = 0; i < 8; i++) {
            float rs = 0.f;
#pragma unroll
            for (int j = 0; j < 8; j++) {
                // matches jnp: round(sim/BIN)*BIN with round-half-even
                float q = rintf(acc[i][j] / 0.05f);
                float e = __expf(q * 0.05f);   // sim bounded: no max-subtraction needed
                acc[i][j] = e;
                rs += e;
            }
            *(float4*)&C[(size_t)(m0 + i) * N + n0]     = *(float4*)&acc[i][0];
            *(float4*)&C[(size_t)(m0 + i) * N + n0 + 4] = *(float4*)&acc[i][4];
            // reduce rs across the 16 threads (tx lanes) sharing this row
#pragma unroll
            for (int m = 1; m < 16; m <<= 1)
                rs += __shfl_xor_sync(0xffffffffu, rs, m);
            if (tx == 0) atomicAdd(&den[m0 + i], rs);
        }
    } else {  // EPI_OUT
#pragma unroll
        for (int i = 0; i < 8; i++) {
            const float sc = 1.0f / den[m0 + i];
#pragma unroll
            for (int j = 0; j < 8; j++) acc[i][j] *= sc;
            *(float4*)&C[(size_t)(m0 + i) * N + n0]     = *(float4*)&acc[i][0];
            *(float4*)&C[(size_t)(m0 + i) * N + n0 + 4] = *(float4*)&acc[i][4];
        }
    }
}

// In-place row L2 normalization, H=512, 128 threads = 1 float4/thread.
__global__ void l2norm_kernel(float* __restrict__ P)
{
    const int r = blockIdx.x;
    float4* row = (float4*)(P + (size_t)r * 512);
    const int t = threadIdx.x;
    float4 v = row[t];
    float ss = v.x * v.x + v.y * v.y + v.z * v.z + v.w * v.w;
#pragma unroll
    for (int m = 16; m; m >>= 1) ss += __shfl_xor_sync(0xffffffffu, ss, m);
    __shared__ float ws[4];
    if ((t & 31) == 0) ws[t >> 5] = ss;
    __syncthreads();
    const float tot = ws[0] + ws[1] + ws[2] + ws[3];
    const float d = fmaxf(sqrtf(tot), 1e-12f);
    v.x /= d; v.y /= d; v.z /= d; v.w /= d;
    row[t] = v;
}

__global__ void zero_kernel(float* __restrict__ p, int n)
{
    const int i = blockIdx.x * blockDim.x + threadIdx.x;
    if (i < n) p[i] = 0.f;
}

extern "C" void kernel_launch(void* const* d_in, const int* in_sizes, int n_in,
                              void* d_out, int out_size)
{
    const float* x       = (const float*)d_in[0];
    const float* anchors = (const float*)d_in[1];
    const float* Wq      = (const float*)d_in[2];
    const float* Wk      = (const float*)d_in[3];
    const float* values  = (const float*)d_in[4];
    float* out = (float*)d_out;

    const int D = 512, H = 512;
    const int B = in_sizes[0] / D;   // 16384
    const int A = in_sizes[1] / D;   // 4096

    float *Qs, *Ks, *Es, *dn;
    cudaGetSymbolAddress((void**)&Qs, g_Q);
    cudaGetSymbolAddress((void**)&Ks, g_Kn);
    cudaGetSymbolAddress((void**)&Es, g_E);
    cudaGetSymbolAddress((void**)&dn, g_den);

    // 1-2) projections
    gemm_kernel<false, EPI_STORE><<<dim3(H / BN, B / BM), 256>>>(x, Wq, Qs, B, H, D, nullptr);
    gemm_kernel<false, EPI_STORE><<<dim3(H / BN, A / BM), 256>>>(anchors, Wk, Ks, A, H, D, nullptr);
    // 3) L2 normalize
    l2norm_kernel<<<B, 128>>>(Qs);
    l2norm_kernel<<<A, 128>>>(Ks);
    // 4) zero denominators
    zero_kernel<<<(B + 255) / 256, 256>>>(dn, B);
    // 5) E = exp(quant(Qn @ Kn^T)), den = rowsum(E)
    gemm_kernel<true, EPI_SIM><<<dim3(A / BN, B / BM), 256>>>(Qs, Ks, Es, B, A, H, dn);
    // 6) out = (E @ values) / den
    gemm_kernel<false, EPI_OUT><<<dim3(H / BN, B / BM), 256>>>(Es, values, out, B, H, A, dn);
}

// round 5
// speedup vs baseline: 2.2377x; 2.2377x over previous
#include <cuda_runtime.h>
#include <cuda_bf16.h>
#include <cstdint>
#include <cstddef>

// ===========================================================================
// RelativeAttention on sm_100 (plain target: NO tcgen05 — legacy mma.sync).
//
// All GEMMs use split-bf16 3-term (hi*hi + hi*lo + lo*hi) with fp32
// accumulation via mma.sync.m16n8k16 (HMMA), cp.async double-buffered smem.
//
//   1) split x, anchors -> bf16 hi/lo;  transpose+split Wq, Wk, values
//   2) Qf = x @ Wq, Kf = anchors @ Wk    (mma, EPI_STORE fp32)
//   3) l2norm rows of Qf/Kf + split -> Q/K bf16 hi/lo
//   4) zero den
//   5) SIM: S = Qn @ Kn^T  -> quantize->exp -> E hi/lo + rowsum atomics
//   6) OUT: O = E @ V^T^T  -> scale by 1/den -> fp32 out
// ===========================================================================

// ------------------------- device scratch ----------------------------------
__device__ float g_Qf[16384 * 512];
__device__ float g_Kf[4096 * 512];
__device__ float g_den[16384];
__device__ __nv_bfloat16 g_xhi[16384 * 512];
__device__ __nv_bfloat16 g_xlo[16384 * 512];
__device__ __nv_bfloat16 g_ahi[4096 * 512];
__device__ __nv_bfloat16 g_alo[4096 * 512];
__device__ __nv_bfloat16 g_Wqthi[512 * 512];
__device__ __nv_bfloat16 g_Wqtlo[512 * 512];
__device__ __nv_bfloat16 g_Wkthi[512 * 512];
__device__ __nv_bfloat16 g_Wktlo[512 * 512];
__device__ __nv_bfloat16 g_Qhi[16384 * 512];
__device__ __nv_bfloat16 g_Qlo[16384 * 512];
__device__ __nv_bfloat16 g_Khi[4096 * 512];
__device__ __nv_bfloat16 g_Klo[4096 * 512];
__device__ __nv_bfloat16 g_Ehi[(size_t)16384 * 4096];
__device__ __nv_bfloat16 g_Elo[(size_t)16384 * 4096];
__device__ __nv_bfloat16 g_Vthi[512 * 4096];
__device__ __nv_bfloat16 g_Vtlo[512 * 4096];

// ------------------------- helpers -----------------------------------------
__device__ __forceinline__ uint32_t s2u(const void* p) {
    uint32_t a;
    asm("{ .reg .u64 t; cvta.to.shared.u64 t, %1; cvt.u32.u64 %0, t; }"
        : "=r"(a) : "l"(p));
    return a;
}

__device__ __forceinline__ void cp16(uint32_t dst, const void* src) {
    asm volatile("cp.async.cg.shared.global [%0], [%1], 16;" :: "r"(dst), "l"(src));
}
#define CP_COMMIT() asm volatile("cp.async.commit_group;" ::: "memory")

__device__ __forceinline__ void mma16816(float* d, const uint32_t* a, const uint32_t* b) {
    asm volatile(
        "mma.sync.aligned.m16n8k16.row.col.f32.bf16.bf16.f32 "
        "{%0,%1,%2,%3}, {%4,%5,%6,%7}, {%8,%9}, {%0,%1,%2,%3};"
        : "+f"(d[0]), "+f"(d[1]), "+f"(d[2]), "+f"(d[3])
        : "r"(a[0]), "r"(a[1]), "r"(a[2]), "r"(a[3]), "r"(b[0]), "r"(b[1]));
}

__device__ __forceinline__ uint32_t pack_bf2(float a, float b) {
    __nv_bfloat16 ha = __float2bfloat16(a), hb = __float2bfloat16(b);
    return (uint32_t)__bfloat16_as_ushort(ha) |
           ((uint32_t)__bfloat16_as_ushort(hb) << 16);
}

// ------------------------- mma GEMM kernel ---------------------------------
// D[M,N] (+epilogue) = Ahi@Bhi^T + Ahi@Blo^T + Alo@Bhi^T
//   A*: [M, K] bf16 row-major; B*: [N, K] bf16 row-major; K % 32 == 0.
// Block 128x128x32, 256 threads, 8 warps (4x2), warp tile 32x64.
// smem: 2 stages x 4 tiles(Ahi,Alo,Bhi,Blo) x 128 rows x 80B (64B data + pad).
// EPI 0 = SIM (quant->exp->E hi/lo + rowsum atomics)
// EPI 1 = OUT (scale 1/den, fp32 store)
// EPI 2 = STORE (fp32 store)
#define ROWB 80
#define TILEB (128 * ROWB)      // 10240
#define STAGEB (4 * TILEB)      // 40960
static constexpr int MMA_SMEM = 2 * STAGEB;   // 81920

__device__ __forceinline__ void load_stage(
    uint32_t sbase, const __nv_bfloat16* Ahi, const __nv_bfloat16* Alo,
    const __nv_bfloat16* Bhi, const __nv_bfloat16* Blo,
    int bm0, int bn0, int K, int c, int tid)
{
    const __nv_bfloat16* gp[4] = { Ahi, Alo, Bhi, Blo };
    const int rb[4] = { bm0, bm0, bn0, bn0 };
    const size_t kb = (size_t)c * 32;
#pragma unroll
    for (int t = 0; t < 8; t++) {
        const int seg  = tid + t * 256;
        const int tile = seg >> 9;
        const int w    = seg & 511;
        const int row  = w >> 2;
        const int c16  = w & 3;
        const __nv_bfloat16* src = gp[tile] + (size_t)(rb[tile] + row) * K + kb + c16 * 8;
        cp16(sbase + tile * TILEB + row * ROWB + c16 * 16, src);
    }
}

template <int EPI>
__global__ __launch_bounds__(256)
void mma_gemm_kernel(const __nv_bfloat16* __restrict__ Ahi,
                     const __nv_bfloat16* __restrict__ Alo,
                     const __nv_bfloat16* __restrict__ Bhi,
                     const __nv_bfloat16* __restrict__ Blo,
                     int K, int ldC,
                     float* __restrict__ den,
                     __nv_bfloat16* __restrict__ Ehi,
                     __nv_bfloat16* __restrict__ Elo,
                     float* __restrict__ Cf)
{
    extern __shared__ char sm[];
    const uint32_t sb = s2u(sm);
    const int tid  = threadIdx.x;
    const int wid  = tid >> 5;
    const int lane = tid & 31;
    const int wm   = wid >> 1;          // 0..3 (M)
    const int wn   = wid & 1;           // 0..1 (N)
    const int g    = lane >> 2;         // 0..7
    const int tg   = lane & 3;          // 0..3
    const int bm0  = blockIdx.y * 128;
    const int bn0  = blockIdx.x * 128;

    float acc[2][8][4];
#pragma unroll
    for (int mt = 0; mt < 2; mt++)
#pragma unroll
        for (int nt = 0; nt < 8; nt++)
#pragma unroll
            for (int j = 0; j < 4; j++) acc[mt][nt][j] = 0.f;

    const int nch = K >> 5;
    load_stage(sb,          Ahi, Alo, Bhi, Blo, bm0, bn0, K, 0, tid);
    CP_COMMIT();
    load_stage(sb + STAGEB, Ahi, Alo, Bhi, Blo, bm0, bn0, K, 1, tid);
    CP_COMMIT();

    for (int c = 0; c < nch; c++) {
        if (c + 1 < nch) asm volatile("cp.async.wait_group 1;" ::: "memory");
        else             asm volatile("cp.async.wait_group 0;" ::: "memory");
        __syncthreads();

        const char* st = sm + (c & 1) * STAGEB;
        const char* Ah = st;
        const char* Al = st + TILEB;
        const char* Bh = st + 2 * TILEB;
        const char* Bl = st + 3 * TILEB;

#pragma unroll
        for (int ks = 0; ks < 2; ks++) {
            const int kb = ks * 32 + tg * 4;
            uint32_t ah[2][4], al[2][4];
#pragma unroll
            for (int mt = 0; mt < 2; mt++) {
                const int r0 = (wm * 32 + mt * 16 + g) * ROWB;
                ah[mt][0] = *(const uint32_t*)(Ah + r0 + kb);
                ah[mt][1] = *(const uint32_t*)(Ah + r0 + 8 * ROWB + kb);
                ah[mt][2] = *(const uint32_t*)(Ah + r0 + kb + 16);
                ah[mt][3] = *(const uint32_t*)(Ah + r0 + 8 * ROWB + kb + 16);
                al[mt][0] = *(const uint32_t*)(Al + r0 + kb);
                al[mt][1] = *(const uint32_t*)(Al + r0 + 8 * ROWB + kb);
                al[mt][2] = *(const uint32_t*)(Al + r0 + kb + 16);
                al[mt][3] = *(const uint32_t*)(Al + r0 + 8 * ROWB + kb + 16);
            }
#pragma unroll
            for (int nt = 0; nt < 8; nt++) {
                const int c0 = (wn * 64 + nt * 8 + g) * ROWB;
                uint32_t bh[2], bl[2];
                bh[0] = *(const uint32_t*)(Bh + c0 + kb);
                bh[1] = *(const uint32_t*)(Bh + c0 + kb + 16);
                bl[0] = *(const uint32_t*)(Bl + c0 + kb);
                bl[1] = *(const uint32_t*)(Bl + c0 + kb + 16);
#pragma unroll
                for (int mt = 0; mt < 2; mt++) {
                    mma16816(acc[mt][nt], ah[mt], bh);
                    mma16816(acc[mt][nt], ah[mt], bl);
                    mma16816(acc[mt][nt], al[mt], bh);
                }
            }
        }
        __syncthreads();
        if (c + 2 < nch) {
            load_stage(sb + (c & 1) * STAGEB, Ahi, Alo, Bhi, Blo, bm0, bn0, K, c + 2, tid);
            CP_COMMIT();
        }
    }

    // ------------------------- epilogue -------------------------
    if constexpr (EPI == 0) {          // SIM
        float rs[2][2] = { {0.f, 0.f}, {0.f, 0.f} };
#pragma unroll
        for (int mt = 0; mt < 2; mt++) {
            const int rh = bm0 + wm * 32 + mt * 16 + g;
            const int rl = rh + 8;
#pragma unroll
            for (int nt = 0; nt < 8; nt++) {
                const int col = bn0 + wn * 64 + nt * 8 + tg * 2;
                float e0 = __expf(rintf(acc[mt][nt][0] / 0.05f) * 0.05f);
                float e1 = __expf(rintf(acc[mt][nt][1] / 0.05f) * 0.05f);
                float e2 = __expf(rintf(acc[mt][nt][2] / 0.05f) * 0.05f);
                float e3 = __expf(rintf(acc[mt][nt][3] / 0.05f) * 0.05f);
                rs[mt][0] += e0 + e1;
                rs[mt][1] += e2 + e3;
                __nv_bfloat16 h0 = __float2bfloat16(e0), h1 = __float2bfloat16(e1);
                __nv_bfloat16 h2 = __float2bfloat16(e2), h3 = __float2bfloat16(e3);
                const size_t oh = (size_t)rh * ldC + col;
                const size_t ol = (size_t)rl * ldC + col;
                *(uint32_t*)(Ehi + oh) = (uint32_t)__bfloat16_as_ushort(h0) |
                                         ((uint32_t)__bfloat16_as_ushort(h1) << 16);
                *(uint32_t*)(Ehi + ol) = (uint32_t)__bfloat16_as_ushort(h2) |
                                         ((uint32_t)__bfloat16_as_ushort(h3) << 16);
                *(uint32_t*)(Elo + oh) = pack_bf2(e0 - __bfloat162float(h0),
                                                  e1 - __bfloat162float(h1));
                *(uint32_t*)(Elo + ol) = pack_bf2(e2 - __bfloat162float(h2),
                                                  e3 - __bfloat162float(h3));
            }
        }
#pragma unroll
        for (int mt = 0; mt < 2; mt++)
#pragma unroll
            for (int hl = 0; hl < 2; hl++) {
                float v = rs[mt][hl];
                v += __shfl_xor_sync(0xffffffffu, v, 1);
                v += __shfl_xor_sync(0xffffffffu, v, 2);
                if (tg == 0)
                    atomicAdd(&den[bm0 + wm * 32 + mt * 16 + g + hl * 8], v);
            }
    } else if constexpr (EPI == 1) {   // OUT: scale by 1/den
#pragma unroll
        for (int mt = 0; mt < 2; mt++) {
            const int rh = bm0 + wm * 32 + mt * 16 + g;
            const int rl = rh + 8;
            const float sh = 1.0f / den[rh];
            const float sl = 1.0f / den[rl];
#pragma unroll
            for (int nt = 0; nt < 8; nt++) {
                const int col = bn0 + wn * 64 + nt * 8 + tg * 2;
                float2 vh = make_float2(acc[mt][nt][0] * sh, acc[mt][nt][1] * sh);
                float2 vl = make_float2(acc[mt][nt][2] * sl, acc[mt][nt][3] * sl);
                *(float2*)(Cf + (size_t)rh * ldC + col) = vh;
                *(float2*)(Cf + (size_t)rl * ldC + col) = vl;
            }
        }
    } else {                           // STORE fp32
#pragma unroll
        for (int mt = 0; mt < 2; mt++) {
            const int rh = bm0 + wm * 32 + mt * 16 + g;
            const int rl = rh + 8;
#pragma unroll
            for (int nt = 0; nt < 8; nt++) {
                const int col = bn0 + wn * 64 + nt * 8 + tg * 2;
                *(float2*)(Cf + (size_t)rh * ldC + col) =
                    make_float2(acc[mt][nt][0], acc[mt][nt][1]);
                *(float2*)(Cf + (size_t)rl * ldC + col) =
                    make_float2(acc[mt][nt][2], acc[mt][nt][3]);
            }
        }
    }
}

// ------------------------- split fp32 -> bf16 hi/lo ------------------------
__global__ void split_kernel(const float* __restrict__ s,
                             __nv_bfloat16* __restrict__ hi,
                             __nv_bfloat16* __restrict__ lo, int n4)
{
    const int i = blockIdx.x * blockDim.x + threadIdx.x;
    if (i >= n4) return;
    float4 v = ((const float4*)s)[i];
    const float f[4] = { v.x, v.y, v.z, v.w };
    uint32_t hp[2], lp[2];
#pragma unroll
    for (int j = 0; j < 2; j++) {
        __nv_bfloat16 h0 = __float2bfloat16(f[2 * j]);
        __nv_bfloat16 h1 = __float2bfloat16(f[2 * j + 1]);
        hp[j] = (uint32_t)__bfloat16_as_ushort(h0) |
                ((uint32_t)__bfloat16_as_ushort(h1) << 16);
        lp[j] = pack_bf2(f[2 * j]     - __bfloat162float(h0),
                         f[2 * j + 1] - __bfloat162float(h1));
    }
    *(uint2*)(hi + (size_t)i * 4) = make_uint2(hp[0], hp[1]);
    *(uint2*)(lo + (size_t)i * 4) = make_uint2(lp[0], lp[1]);
}

// ----------------- transpose + split: src[R,C] -> out[C,R] bf16 ------------
__global__ void trans_split_kernel(const float* __restrict__ src,
                                   __nv_bfloat16* __restrict__ hi,
                                   __nv_bfloat16* __restrict__ lo,
                                   int R, int C)
{
    __shared__ float t[32][33];
    const int c0 = blockIdx.x * 32, r0 = blockIdx.y * 32;
    const int tx = threadIdx.x, ty = threadIdx.y;   // 32 x 8
#pragma unroll
    for (int j = 0; j < 32; j += 8)
        t[ty + j][tx] = src[(size_t)(r0 + ty + j) * C + c0 + tx];
    __syncthreads();
#pragma unroll
    for (int j = 0; j < 32; j += 8) {
        const float v = t[tx][ty + j];
        __nv_bfloat16 h = __float2bfloat16(v);
        const size_t o = (size_t)(c0 + ty + j) * R + r0 + tx;
        hi[o] = h;
        lo[o] = __float2bfloat16(v - __bfloat162float(h));
    }
}

// ------------------------- l2 normalize + split ----------------------------
__global__ void l2norm_split_kernel(const float* __restrict__ P,
                                    __nv_bfloat16* __restrict__ hi,
                                    __nv_bfloat16* __restrict__ lo)
{
    const int r = blockIdx.x;
    const int t = threadIdx.x;  // 128 threads x float4 (H=512)
    const float4 v = ((const float4*)(P + (size_t)r * 512))[t];
    float ss = v.x * v.x + v.y * v.y + v.z * v.z + v.w * v.w;
#pragma unroll
    for (int m = 16; m; m >>= 1) ss += __shfl_xor_sync(0xffffffffu, ss, m);
    __shared__ float ws[4];
    if ((t & 31) == 0) ws[t >> 5] = ss;
    __syncthreads();
    const float d = fmaxf(sqrtf(ws[0] + ws[1] + ws[2] + ws[3]), 1e-12f);
    const float f[4] = { v.x / d, v.y / d, v.z / d, v.w / d };
    uint32_t hp[2], lp[2];
#pragma unroll
    for (int j = 0; j < 2; j++) {
        __nv_bfloat16 h0 = __float2bfloat16(f[2 * j]);
        __nv_bfloat16 h1 = __float2bfloat16(f[2 * j + 1]);
        hp[j] = (uint32_t)__bfloat16_as_ushort(h0) |
                ((uint32_t)__bfloat16_as_ushort(h1) << 16);
        lp[j] = pack_bf2(f[2 * j]     - __bfloat162float(h0),
                         f[2 * j + 1] - __bfloat162float(h1));
    }
    const size_t off = (size_t)r * 512 + t * 4;
    *(uint2*)(hi + off) = make_uint2(hp[0], hp[1]);
    *(uint2*)(lo + off) = make_uint2(lp[0], lp[1]);
}

__global__ void zero_kernel(float* __restrict__ p, int n)
{
    const int i = blockIdx.x * blockDim.x + threadIdx.x;
    if (i < n) p[i] = 0.f;
}

// ------------------------- launch ------------------------------------------
extern "C" void kernel_launch(void* const* d_in, const int* in_sizes, int n_in,
                              void* d_out, int out_size)
{
    const float* x       = (const float*)d_in[0];
    const float* anchors = (const float*)d_in[1];
    const float* Wq      = (const float*)d_in[2];
    const float* Wk      = (const float*)d_in[3];
    const float* values  = (const float*)d_in[4];
    float* out = (float*)d_out;

    const int D = 512, H = 512;
    const int B = in_sizes[0] / D;   // 16384
    const int A = in_sizes[1] / D;   // 4096

    float *Qf, *Kf, *dn;
    __nv_bfloat16 *xhi, *xlo, *ahi, *alo, *Wqthi, *Wqtlo, *Wkthi, *Wktlo;
    __nv_bfloat16 *Qhi, *Qlo, *Khi, *Klo, *Ehi, *Elo, *Vthi, *Vtlo;
    cudaGetSymbolAddress((void**)&Qf,    g_Qf);
    cudaGetSymbolAddress((void**)&Kf,    g_Kf);
    cudaGetSymbolAddress((void**)&dn,    g_den);
    cudaGetSymbolAddress((void**)&xhi,   g_xhi);
    cudaGetSymbolAddress((void**)&xlo,   g_xlo);
    cudaGetSymbolAddress((void**)&ahi,   g_ahi);
    cudaGetSymbolAddress((void**)&alo,   g_alo);
    cudaGetSymbolAddress((void**)&Wqthi, g_Wqthi);
    cudaGetSymbolAddress((void**)&Wqtlo, g_Wqtlo);
    cudaGetSymbolAddress((void**)&Wkthi, g_Wkthi);
    cudaGetSymbolAddress((void**)&Wktlo, g_Wktlo);
    cudaGetSymbolAddress((void**)&Qhi,   g_Qhi);
    cudaGetSymbolAddress((void**)&Qlo,   g_Qlo);
    cudaGetSymbolAddress((void**)&Khi,   g_Khi);
    cudaGetSymbolAddress((void**)&Klo,   g_Klo);
    cudaGetSymbolAddress((void**)&Ehi,   g_Ehi);
    cudaGetSymbolAddress((void**)&Elo,   g_Elo);
    cudaGetSymbolAddress((void**)&Vthi,  g_Vthi);
    cudaGetSymbolAddress((void**)&Vtlo,  g_Vtlo);

    cudaFuncSetAttribute(mma_gemm_kernel<0>,
                         cudaFuncAttributeMaxDynamicSharedMemorySize, MMA_SMEM);
    cudaFuncSetAttribute(mma_gemm_kernel<1>,
                         cudaFuncAttributeMaxDynamicSharedMemorySize, MMA_SMEM);
    cudaFuncSetAttribute(mma_gemm_kernel<2>,
                         cudaFuncAttributeMaxDynamicSharedMemorySize, MMA_SMEM);

    // 1) splits / transposes
    split_kernel<<<(B * D / 4 + 255) / 256, 256>>>(x, xhi, xlo, B * D / 4);
    split_kernel<<<(A * D / 4 + 255) / 256, 256>>>(anchors, ahi, alo, A * D / 4);
    trans_split_kernel<<<dim3(H / 32, D / 32), dim3(32, 8)>>>(Wq, Wqthi, Wqtlo, D, H);
    trans_split_kernel<<<dim3(H / 32, D / 32), dim3(32, 8)>>>(Wk, Wkthi, Wktlo, D, H);
    trans_split_kernel<<<dim3(H / 32, A / 32), dim3(32, 8)>>>(values, Vthi, Vtlo, A, H);

    // 2) projections (mma, fp32 store)
    mma_gemm_kernel<2><<<dim3(H / 128, B / 128), 256, MMA_SMEM>>>(
        xhi, xlo, Wqthi, Wqtlo, D, H, nullptr, nullptr, nullptr, Qf);
    mma_gemm_kernel<2><<<dim3(H / 128, A / 128), 256, MMA_SMEM>>>(
        ahi, alo, Wkthi, Wktlo, D, H, nullptr, nullptr, nullptr, Kf);

    // 3) l2 normalize + split
    l2norm_split_kernel<<<B, 128>>>(Qf, Qhi, Qlo);
    l2norm_split_kernel<<<A, 128>>>(Kf, Khi, Klo);

    // 4) zero den
    zero_kernel<<<(B + 255) / 256, 256>>>(dn, B);

    // 5) SIM: E = exp(quant(Qn @ Kn^T)), den = rowsum
    mma_gemm_kernel<0><<<dim3(A / 128, B / 128), 256, MMA_SMEM>>>(
        Qhi, Qlo, Khi, Klo, H, A, dn, Ehi, Elo, nullptr);

    // 6) OUT: out = (E @ V) / den
    mma_gemm_kernel<1><<<dim3(H / 128, B / 128), 256, MMA_SMEM>>>(
        Ehi, Elo, Vthi, Vtlo, A, H, dn, nullptr, nullptr, out);
}

// round 6
// speedup vs baseline: 3.0840x; 1.3782x over previous
#include <cuda_runtime.h>
#include <cuda_bf16.h>
#include <cuda_fp16.h>
#include <cstdint>
#include <cstddef>

// ===========================================================================
// RelativeAttention on sm_100 (plain target: legacy mma.sync / HMMA).
//
//   1) split x, anchors -> bf16 hi/lo;  transpose+split Wq, Wk (bf16 hi/lo);
//      transpose values -> Vt fp16
//   2) Qf = x @ Wq, Kf = anchors @ Wk    (3-term bf16 mma, fp32 store)
//   3) l2norm rows of Qf/Kf + split -> Q/K bf16 hi/lo
//   4) zero den
//   5) SIM (3-term bf16): S = Qn @ Kn^T -> quant->exp -> E fp16 + rowsum atomics
//   6) OUT (1-term fp16): O = E @ Vt^T -> scale by 1/den -> fp32 out
// ===========================================================================

// ------------------------- device scratch ----------------------------------
__device__ float g_Qf[16384 * 512];
__device__ float g_Kf[4096 * 512];
__device__ float g_den[16384];
__device__ __nv_bfloat16 g_xhi[16384 * 512];
__device__ __nv_bfloat16 g_xlo[16384 * 512];
__device__ __nv_bfloat16 g_ahi[4096 * 512];
__device__ __nv_bfloat16 g_alo[4096 * 512];
__device__ __nv_bfloat16 g_Wqthi[512 * 512];
__device__ __nv_bfloat16 g_Wqtlo[512 * 512];
__device__ __nv_bfloat16 g_Wkthi[512 * 512];
__device__ __nv_bfloat16 g_Wktlo[512 * 512];
__device__ __nv_bfloat16 g_Qhi[16384 * 512];
__device__ __nv_bfloat16 g_Qlo[16384 * 512];
__device__ __nv_bfloat16 g_Khi[4096 * 512];
__device__ __nv_bfloat16 g_Klo[4096 * 512];
__device__ __half g_E[(size_t)16384 * 4096];
__device__ __half g_Vt[512 * 4096];

// ------------------------- helpers -----------------------------------------
__device__ __forceinline__ uint32_t s2u(const void* p) {
    uint32_t a;
    asm("{ .reg .u64 t; cvta.to.shared.u64 t, %1; cvt.u32.u64 %0, t; }"
        : "=r"(a) : "l"(p));
    return a;
}

__device__ __forceinline__ void cp16(uint32_t dst, const void* src) {
    asm volatile("cp.async.cg.shared.global [%0], [%1], 16;" :: "r"(dst), "l"(src));
}
#define CP_COMMIT() asm volatile("cp.async.commit_group;" ::: "memory")
#define CP_WAIT2()  asm volatile("cp.async.wait_group 2;" ::: "memory")

__device__ __forceinline__ void mma_bf16(float* d, const uint32_t* a, const uint32_t* b) {
    asm volatile(
        "mma.sync.aligned.m16n8k16.row.col.f32.bf16.bf16.f32 "
        "{%0,%1,%2,%3}, {%4,%5,%6,%7}, {%8,%9}, {%0,%1,%2,%3};"
        : "+f"(d[0]), "+f"(d[1]), "+f"(d[2]), "+f"(d[3])
        : "r"(a[0]), "r"(a[1]), "r"(a[2]), "r"(a[3]), "r"(b[0]), "r"(b[1]));
}

__device__ __forceinline__ void mma_f16(float* d, const uint32_t* a, const uint32_t* b) {
    asm volatile(
        "mma.sync.aligned.m16n8k16.row.col.f32.f16.f16.f32 "
        "{%0,%1,%2,%3}, {%4,%5,%6,%7}, {%8,%9}, {%0,%1,%2,%3};"
        : "+f"(d[0]), "+f"(d[1]), "+f"(d[2]), "+f"(d[3])
        : "r"(a[0]), "r"(a[1]), "r"(a[2]), "r"(a[3]), "r"(b[0]), "r"(b[1]));
}

__device__ __forceinline__ uint32_t pack_bf2(float a, float b) {
    __nv_bfloat16 ha = __float2bfloat16(a), hb = __float2bfloat16(b);
    return (uint32_t)__bfloat16_as_ushort(ha) |
           ((uint32_t)__bfloat16_as_ushort(hb) << 16);
}
__device__ __forceinline__ uint32_t pack_h2(float a, float b) {
    __half2 h = __floats2half2_rn(a, b);
    return *(uint32_t*)&h;
}

// ------------------------- shared tiling constants --------------------------
// 128x128x32 block tile, 256 threads, 8 warps (4x2 M x N), warp tile 32x64.
// smem rows: 64B data (32 elems x 2B) + 16B pad = 80B -> conflict-free LDS.32.
#define ROWB 80
#define TILEB (128 * ROWB)              // 10240 per tile
#define STAGE3 (4 * TILEB)              // 40960 (Ahi,Alo,Bhi,Blo)
#define STAGE1 (2 * TILEB)              // 20480 (A,B)
static constexpr int SMEM3 = 3 * STAGE3;   // 122880
static constexpr int SMEM1 = 3 * STAGE1;   // 61440

// ------------------------- 3-term bf16 GEMM kernel --------------------------
// D = Ahi@Bhi^T + Ahi@Blo^T + Alo@Bhi^T
// EPI 0 = SIM (quant->exp -> E fp16 + rowsum atomics), EPI 2 = STORE fp32.
__device__ __forceinline__ void load_stage4(
    uint32_t sbase, const __nv_bfloat16* Ahi, const __nv_bfloat16* Alo,
    const __nv_bfloat16* Bhi, const __nv_bfloat16* Blo,
    int bm0, int bn0, int K, int c, int tid)
{
    const __nv_bfloat16* gp[4] = { Ahi, Alo, Bhi, Blo };
    const int rb[4] = { bm0, bm0, bn0, bn0 };
    const size_t kb = (size_t)c * 32;
#pragma unroll
    for (int t = 0; t < 8; t++) {
        const int seg  = tid + t * 256;
        const int tile = seg >> 9;
        const int w    = seg & 511;
        const int row  = w >> 2;
        const int c16  = w & 3;
        const __nv_bfloat16* src = gp[tile] + (size_t)(rb[tile] + row) * K + kb + c16 * 8;
        cp16(sbase + tile * TILEB + row * ROWB + c16 * 16, src);
    }
}

template <int EPI>
__global__ __launch_bounds__(256)
void mma3_kernel(const __nv_bfloat16* __restrict__ Ahi,
                 const __nv_bfloat16* __restrict__ Alo,
                 const __nv_bfloat16* __restrict__ Bhi,
                 const __nv_bfloat16* __restrict__ Blo,
                 int K, int ldC,
                 float* __restrict__ den,
                 __half* __restrict__ E,
                 float* __restrict__ Cf)
{
    extern __shared__ char sm[];
    const uint32_t sb = s2u(sm);
    const int tid  = threadIdx.x;
    const int wid  = tid >> 5;
    const int lane = tid & 31;
    const int wm   = wid >> 1;          // 0..3 (M)
    const int wn   = wid & 1;           // 0..1 (N)
    const int g    = lane >> 2;         // 0..7
    const int tg   = lane & 3;          // 0..3
    const int bm0  = blockIdx.y * 128;
    const int bn0  = blockIdx.x * 128;

    float acc[2][8][4];
#pragma unroll
    for (int mt = 0; mt < 2; mt++)
#pragma unroll
        for (int nt = 0; nt < 8; nt++)
#pragma unroll
            for (int j = 0; j < 4; j++) acc[mt][nt][j] = 0.f;

    const int nch = K >> 5;
#pragma unroll
    for (int s = 0; s < 3; s++) {
        load_stage4(sb + s * STAGE3, Ahi, Alo, Bhi, Blo, bm0, bn0, K, s, tid);
        CP_COMMIT();
    }

    int stg = 0;
    for (int c = 0; c < nch; c++) {
        CP_WAIT2();
        __syncthreads();

        const char* st = sm + stg * STAGE3;
        const char* Ah = st;
        const char* Al = st + TILEB;
        const char* Bh = st + 2 * TILEB;
        const char* Bl = st + 3 * TILEB;

#pragma unroll
        for (int ks = 0; ks < 2; ks++) {
            const int kb = ks * 32 + tg * 4;
            uint32_t ah[2][4], al[2][4];
#pragma unroll
            for (int mt = 0; mt < 2; mt++) {
                const int r0 = (wm * 32 + mt * 16 + g) * ROWB;
                ah[mt][0] = *(const uint32_t*)(Ah + r0 + kb);
                ah[mt][1] = *(const uint32_t*)(Ah + r0 + 8 * ROWB + kb);
                ah[mt][2] = *(const uint32_t*)(Ah + r0 + kb + 16);
                ah[mt][3] = *(const uint32_t*)(Ah + r0 + 8 * ROWB + kb + 16);
                al[mt][0] = *(const uint32_t*)(Al + r0 + kb);
                al[mt][1] = *(const uint32_t*)(Al + r0 + 8 * ROWB + kb);
                al[mt][2] = *(const uint32_t*)(Al + r0 + kb + 16);
                al[mt][3] = *(const uint32_t*)(Al + r0 + 8 * ROWB + kb + 16);
            }
#pragma unroll
            for (int nt = 0; nt < 8; nt++) {
                const int c0 = (wn * 64 + nt * 8 + g) * ROWB;
                uint32_t bh[2], bl[2];
                bh[0] = *(const uint32_t*)(Bh + c0 + kb);
                bh[1] = *(const uint32_t*)(Bh + c0 + kb + 16);
                bl[0] = *(const uint32_t*)(Bl + c0 + kb);
                bl[1] = *(const uint32_t*)(Bl + c0 + kb + 16);
#pragma unroll
                for (int mt = 0; mt < 2; mt++) {
                    mma_bf16(acc[mt][nt], ah[mt], bh);
                    mma_bf16(acc[mt][nt], ah[mt], bl);
                    mma_bf16(acc[mt][nt], al[mt], bh);
                }
            }
        }
        __syncthreads();
        if (c + 3 < nch)
            load_stage4(sb + stg * STAGE3, Ahi, Alo, Bhi, Blo, bm0, bn0, K, c + 3, tid);
        CP_COMMIT();
        stg = (stg == 2) ? 0 : stg + 1;
    }

    // ------------------------- epilogue -------------------------
    if constexpr (EPI == 0) {          // SIM -> E fp16 + den
        float rs[2][2] = { {0.f, 0.f}, {0.f, 0.f} };
#pragma unroll
        for (int mt = 0; mt < 2; mt++) {
            const int rh = bm0 + wm * 32 + mt * 16 + g;
            const int rl = rh + 8;
#pragma unroll
            for (int nt = 0; nt < 8; nt++) {
                const int col = bn0 + wn * 64 + nt * 8 + tg * 2;
                float e0 = __expf(rintf(acc[mt][nt][0] / 0.05f) * 0.05f);
                float e1 = __expf(rintf(acc[mt][nt][1] / 0.05f) * 0.05f);
                float e2 = __expf(rintf(acc[mt][nt][2] / 0.05f) * 0.05f);
                float e3 = __expf(rintf(acc[mt][nt][3] / 0.05f) * 0.05f);
                rs[mt][0] += e0 + e1;
                rs[mt][1] += e2 + e3;
                *(uint32_t*)(E + (size_t)rh * ldC + col) = pack_h2(e0, e1);
                *(uint32_t*)(E + (size_t)rl * ldC + col) = pack_h2(e2, e3);
            }
        }
#pragma unroll
        for (int mt = 0; mt < 2; mt++)
#pragma unroll
            for (int hl = 0; hl < 2; hl++) {
                float v = rs[mt][hl];
                v += __shfl_xor_sync(0xffffffffu, v, 1);
                v += __shfl_xor_sync(0xffffffffu, v, 2);
                if (tg == 0)
                    atomicAdd(&den[bm0 + wm * 32 + mt * 16 + g + hl * 8], v);
            }
    } else {                           // STORE fp32
#pragma unroll
        for (int mt = 0; mt < 2; mt++) {
            const int rh = bm0 + wm * 32 + mt * 16 + g;
            const int rl = rh + 8;
#pragma unroll
            for (int nt = 0; nt < 8; nt++) {
                const int col = bn0 + wn * 64 + nt * 8 + tg * 2;
                *(float2*)(Cf + (size_t)rh * ldC + col) =
                    make_float2(acc[mt][nt][0], acc[mt][nt][1]);
                *(float2*)(Cf + (size_t)rl * ldC + col) =
                    make_float2(acc[mt][nt][2], acc[mt][nt][3]);
            }
        }
    }
}

// ------------------------- 1-term fp16 OUT kernel ---------------------------
// C = (A @ B^T) / den   (A = E fp16 [M,K], B = Vt fp16 [N,K])
__device__ __forceinline__ void load_stage2(
    uint32_t sbase, const __half* A, const __half* B,
    int bm0, int bn0, int K, int c, int tid)
{
    const __half* gp[2] = { A, B };
    const int rb[2] = { bm0, bn0 };
    const size_t kb = (size_t)c * 32;
#pragma unroll
    for (int t = 0; t < 4; t++) {
        const int seg  = tid + t * 256;
        const int tile = seg >> 9;
        const int w    = seg & 511;
        const int row  = w >> 2;
        const int c16  = w & 3;
        const __half* src = gp[tile] + (size_t)(rb[tile] + row) * K + kb + c16 * 8;
        cp16(sbase + tile * TILEB + row * ROWB + c16 * 16, src);
    }
}

__global__ __launch_bounds__(256, 2)
void out1_kernel(const __half* __restrict__ E,
                 const __half* __restrict__ Vt,
                 int K, int ldC,
                 const float* __restrict__ den,
                 float* __restrict__ Cf)
{
    extern __shared__ char sm[];
    const uint32_t sb = s2u(sm);
    const int tid  = threadIdx.x;
    const int wid  = tid >> 5;
    const int lane = tid & 31;
    const int wm   = wid >> 1;
    const int wn   = wid & 1;
    const int g    = lane >> 2;
    const int tg   = lane & 3;
    const int bm0  = blockIdx.y * 128;
    const int bn0  = blockIdx.x * 128;

    float acc[2][8][4];
#pragma unroll
    for (int mt = 0; mt < 2; mt++)
#pragma unroll
        for (int nt = 0; nt < 8; nt++)
#pragma unroll
            for (int j = 0; j < 4; j++) acc[mt][nt][j] = 0.f;

    const int nch = K >> 5;
#pragma unroll
    for (int s = 0; s < 3; s++) {
        load_stage2(sb + s * STAGE1, E, Vt, bm0, bn0, K, s, tid);
        CP_COMMIT();
    }

    int stg = 0;
    for (int c = 0; c < nch; c++) {
        CP_WAIT2();
        __syncthreads();

        const char* st = sm + stg * STAGE1;
        const char* Ah = st;
        const char* Bh = st + TILEB;

#pragma unroll
        for (int ks = 0; ks < 2; ks++) {
            const int kb = ks * 32 + tg * 4;
            uint32_t ah[2][4];
#pragma unroll
            for (int mt = 0; mt < 2; mt++) {
                const int r0 = (wm * 32 + mt * 16 + g) * ROWB;
                ah[mt][0] = *(const uint32_t*)(Ah + r0 + kb);
                ah[mt][1] = *(const uint32_t*)(Ah + r0 + 8 * ROWB + kb);
                ah[mt][2] = *(const uint32_t*)(Ah + r0 + kb + 16);
                ah[mt][3] = *(const uint32_t*)(Ah + r0 + 8 * ROWB + kb + 16);
            }
#pragma unroll
            for (int nt = 0; nt < 8; nt++) {
                const int c0 = (wn * 64 + nt * 8 + g) * ROWB;
                uint32_t bh[2];
                bh[0] = *(const uint32_t*)(Bh + c0 + kb);
                bh[1] = *(const uint32_t*)(Bh + c0 + kb + 16);
#pragma unroll
                for (int mt = 0; mt < 2; mt++)
                    mma_f16(acc[mt][nt], ah[mt], bh);
            }
        }
        __syncthreads();
        if (c + 3 < nch)
            load_stage2(sb + stg * STAGE1, E, Vt, bm0, bn0, K, c + 3, tid);
        CP_COMMIT();
        stg = (stg == 2) ? 0 : stg + 1;
    }

#pragma unroll
    for (int mt = 0; mt < 2; mt++) {
        const int rh = bm0 + wm * 32 + mt * 16 + g;
        const int rl = rh + 8;
        const float sh = 1.0f / den[rh];
        const float sl = 1.0f / den[rl];
#pragma unroll
        for (int nt = 0; nt < 8; nt++) {
            const int col = bn0 + wn * 64 + nt * 8 + tg * 2;
            *(float2*)(Cf + (size_t)rh * ldC + col) =
                make_float2(acc[mt][nt][0] * sh, acc[mt][nt][1] * sh);
            *(float2*)(Cf + (size_t)rl * ldC + col) =
                make_float2(acc[mt][nt][2] * sl, acc[mt][nt][3] * sl);
        }
    }
}

// ------------------------- split fp32 -> bf16 hi/lo -------------------------
__global__ void split_kernel(const float* __restrict__ s,
                             __nv_bfloat16* __restrict__ hi,
                             __nv_bfloat16* __restrict__ lo, int n4)
{
    const int i = blockIdx.x * blockDim.x + threadIdx.x;
    if (i >= n4) return;
    float4 v = ((const float4*)s)[i];
    const float f[4] = { v.x, v.y, v.z, v.w };
    uint32_t hp[2], lp[2];
#pragma unroll
    for (int j = 0; j < 2; j++) {
        __nv_bfloat16 h0 = __float2bfloat16(f[2 * j]);
        __nv_bfloat16 h1 = __float2bfloat16(f[2 * j + 1]);
        hp[j] = (uint32_t)__bfloat16_as_ushort(h0) |
                ((uint32_t)__bfloat16_as_ushort(h1) << 16);
        lp[j] = pack_bf2(f[2 * j]     - __bfloat162float(h0),
                         f[2 * j + 1] - __bfloat162float(h1));
    }
    *(uint2*)(hi + (size_t)i * 4) = make_uint2(hp[0], hp[1]);
    *(uint2*)(lo + (size_t)i * 4) = make_uint2(lp[0], lp[1]);
}

// ----------------- transpose + split: src[R,C] -> out[C,R] bf16 hi/lo -------
__global__ void trans_split_kernel(const float* __restrict__ src,
                                   __nv_bfloat16* __restrict__ hi,
                                   __nv_bfloat16* __restrict__ lo,
                                   int R, int C)
{
    __shared__ float t[32][33];
    const int c0 = blockIdx.x * 32, r0 = blockIdx.y * 32;
    const int tx = threadIdx.x, ty = threadIdx.y;   // 32 x 8
#pragma unroll
    for (int j = 0; j < 32; j += 8)
        t[ty + j][tx] = src[(size_t)(r0 + ty + j) * C + c0 + tx];
    __syncthreads();
#pragma unroll
    for (int j = 0; j < 32; j += 8) {
        const float v = t[tx][ty + j];
        __nv_bfloat16 h = __float2bfloat16(v);
        const size_t o = (size_t)(c0 + ty + j) * R + r0 + tx;
        hi[o] = h;
        lo[o] = __float2bfloat16(v - __bfloat162float(h));
    }
}

// ----------------- transpose: src[R,C] fp32 -> out[C,R] fp16 ----------------
__global__ void trans_half_kernel(const float* __restrict__ src,
                                  __half* __restrict__ dst,
                                  int R, int C)
{
    __shared__ float t[32][33];
    const int c0 = blockIdx.x * 32, r0 = blockIdx.y * 32;
    const int tx = threadIdx.x, ty = threadIdx.y;   // 32 x 8
#pragma unroll
    for (int j = 0; j < 32; j += 8)
        t[ty + j][tx] = src[(size_t)(r0 + ty + j) * C + c0 + tx];
    __syncthreads();
#pragma unroll
    for (int j = 0; j < 32; j += 8)
        dst[(size_t)(c0 + ty + j) * R + r0 + tx] = __float2half_rn(t[tx][ty + j]);
}

// ------------------------- l2 normalize + split -----------------------------
__global__ void l2norm_split_kernel(const float* __restrict__ P,
                                    __nv_bfloat16* __restrict__ hi,
                                    __nv_bfloat16* __restrict__ lo)
{
    const int r = blockIdx.x;
    const int t = threadIdx.x;  // 128 threads x float4 (H=512)
    const float4 v = ((const float4*)(P + (size_t)r * 512))[t];
    float ss = v.x * v.x + v.y * v.y + v.z * v.z + v.w * v.w;
#pragma unroll
    for (int m = 16; m; m >>= 1) ss += __shfl_xor_sync(0xffffffffu, ss, m);
    __shared__ float ws[4];
    if ((t & 31) == 0) ws[t >> 5] = ss;
    __syncthreads();
    const float d = fmaxf(sqrtf(ws[0] + ws[1] + ws[2] + ws[3]), 1e-12f);
    const float f[4] = { v.x / d, v.y / d, v.z / d, v.w / d };
    uint32_t hp[2], lp[2];
#pragma unroll
    for (int j = 0; j < 2; j++) {
        __nv_bfloat16 h0 = __float2bfloat16(f[2 * j]);
        __nv_bfloat16 h1 = __float2bfloat16(f[2 * j + 1]);
        hp[j] = (uint32_t)__bfloat16_as_ushort(h0) |
                ((uint32_t)__bfloat16_as_ushort(h1) << 16);
        lp[j] = pack_bf2(f[2 * j]     - __bfloat162float(h0),
                         f[2 * j + 1] - __bfloat162float(h1));
    }
    const size_t off = (size_t)r * 512 + t * 4;
    *(uint2*)(hi + off) = make_uint2(hp[0], hp[1]);
    *(uint2*)(lo + off) = make_uint2(lp[0], lp[1]);
}

__global__ void zero_kernel(float* __restrict__ p, int n)
{
    const int i = blockIdx.x * blockDim.x + threadIdx.x;
    if (i < n) p[i] = 0.f;
}

// ------------------------- launch -------------------------------------------
extern "C" void kernel_launch(void* const* d_in, const int* in_sizes, int n_in,
                              void* d_out, int out_size)
{
    const float* x       = (const float*)d_in[0];
    const float* anchors = (const float*)d_in[1];
    const float* Wq      = (const float*)d_in[2];
    const float* Wk      = (const float*)d_in[3];
    const float* values  = (const float*)d_in[4];
    float* out = (float*)d_out;

    const int D = 512, H = 512;
    const int B = in_sizes[0] / D;   // 16384
    const int A = in_sizes[1] / D;   // 4096

    float *Qf, *Kf, *dn;
    __nv_bfloat16 *xhi, *xlo, *ahi, *alo, *Wqthi, *Wqtlo, *Wkthi, *Wktlo;
    __nv_bfloat16 *Qhi, *Qlo, *Khi, *Klo;
    __half *E, *Vt;
    cudaGetSymbolAddress((void**)&Qf,    g_Qf);
    cudaGetSymbolAddress((void**)&Kf,    g_Kf);
    cudaGetSymbolAddress((void**)&dn,    g_den);
    cudaGetSymbolAddress((void**)&xhi,   g_xhi);
    cudaGetSymbolAddress((void**)&xlo,   g_xlo);
    cudaGetSymbolAddress((void**)&ahi,   g_ahi);
    cudaGetSymbolAddress((void**)&alo,   g_alo);
    cudaGetSymbolAddress((void**)&Wqthi, g_Wqthi);
    cudaGetSymbolAddress((void**)&Wqtlo, g_Wqtlo);
    cudaGetSymbolAddress((void**)&Wkthi, g_Wkthi);
    cudaGetSymbolAddress((void**)&Wktlo, g_Wktlo);
    cudaGetSymbolAddress((void**)&Qhi,   g_Qhi);
    cudaGetSymbolAddress((void**)&Qlo,   g_Qlo);
    cudaGetSymbolAddress((void**)&Khi,   g_Khi);
    cudaGetSymbolAddress((void**)&Klo,   g_Klo);
    cudaGetSymbolAddress((void**)&E,     g_E);
    cudaGetSymbolAddress((void**)&Vt,    g_Vt);

    cudaFuncSetAttribute(mma3_kernel<0>,
                         cudaFuncAttributeMaxDynamicSharedMemorySize, SMEM3);
    cudaFuncSetAttribute(mma3_kernel<2>,
                         cudaFuncAttributeMaxDynamicSharedMemorySize, SMEM3);
    cudaFuncSetAttribute(out1_kernel,
                         cudaFuncAttributeMaxDynamicSharedMemorySize, SMEM1);

    // 1) splits / transposes
    split_kernel<<<(B * D / 4 + 255) / 256, 256>>>(x, xhi, xlo, B * D / 4);
    split_kernel<<<(A * D / 4 + 255) / 256, 256>>>(anchors, ahi, alo, A * D / 4);
    trans_split_kernel<<<dim3(H / 32, D / 32), dim3(32, 8)>>>(Wq, Wqthi, Wqtlo, D, H);
    trans_split_kernel<<<dim3(H / 32, D / 32), dim3(32, 8)>>>(Wk, Wkthi, Wktlo, D, H);
    trans_half_kernel<<<dim3(H / 32, A / 32), dim3(32, 8)>>>(values, Vt, A, H);

    // 2) projections (3-term bf16 mma, fp32 store)
    mma3_kernel<2><<<dim3(H / 128, B / 128), 256, SMEM3>>>(
        xhi, xlo, Wqthi, Wqtlo, D, H, nullptr, nullptr, Qf);
    mma3_kernel<2><<<dim3(H / 128, A / 128), 256, SMEM3>>>(
        ahi, alo, Wkthi, Wktlo, D, H, nullptr, nullptr, Kf);

    // 3) l2 normalize + split
    l2norm_split_kernel<<<B, 128>>>(Qf, Qhi, Qlo);
    l2norm_split_kernel<<<A, 128>>>(Kf, Khi, Klo);

    // 4) zero den
    zero_kernel<<<(B + 255) / 256, 256>>>(dn, B);

    // 5) SIM: E = exp(quant(Qn @ Kn^T)) fp16, den = rowsum
    mma3_kernel<0><<<dim3(A / 128, B / 128), 256, SMEM3>>>(
        Qhi, Qlo, Khi, Klo, H, A, dn, E, nullptr);

    // 6) OUT: out = (E @ V) / den  (1-term fp16)
    out1_kernel<<<dim3(H / 128, B / 128), 256, SMEM1>>>(
        E, Vt, A, H, dn, out);
}

// round 7
// speedup vs baseline: 3.7715x; 1.2229x over previous
#include <cuda_runtime.h>
#include <cuda_bf16.h>
#include <cuda_fp16.h>
#include <cstdint>
#include <cstddef>

// ===========================================================================
// RelativeAttention on sm_100 (plain target: legacy mma.sync / HMMA).
// R7: ldmatrix.x4 fragment loads + 2-stage smem + 2 CTAs/SM.
//
//   1) split x, anchors -> bf16 hi/lo; transpose+split Wq, Wk; values -> Vt fp16
//   2) Qf = x @ Wq, Kf = anchors @ Wk    (3-term bf16 mma, fp32 store)
//   3) l2norm rows + split -> Q/K bf16 hi/lo
//   4) zero den
//   5) SIM (3-term bf16): quant->exp -> E fp16 + rowsum atomics
//   6) OUT (1-term fp16): O = E @ Vt^T -> scale 1/den -> fp32 out
// ===========================================================================

// ------------------------- device scratch ----------------------------------
__device__ float g_Qf[16384 * 512];
__device__ float g_Kf[4096 * 512];
__device__ float g_den[16384];
__device__ __nv_bfloat16 g_xhi[16384 * 512];
__device__ __nv_bfloat16 g_xlo[16384 * 512];
__device__ __nv_bfloat16 g_ahi[4096 * 512];
__device__ __nv_bfloat16 g_alo[4096 * 512];
__device__ __nv_bfloat16 g_Wqthi[512 * 512];
__device__ __nv_bfloat16 g_Wqtlo[512 * 512];
__device__ __nv_bfloat16 g_Wkthi[512 * 512];
__device__ __nv_bfloat16 g_Wktlo[512 * 512];
__device__ __nv_bfloat16 g_Qhi[16384 * 512];
__device__ __nv_bfloat16 g_Qlo[16384 * 512];
__device__ __nv_bfloat16 g_Khi[4096 * 512];
__device__ __nv_bfloat16 g_Klo[4096 * 512];
__device__ __half g_E[(size_t)16384 * 4096];
__device__ __half g_Vt[512 * 4096];

// ------------------------- helpers -----------------------------------------
__device__ __forceinline__ uint32_t s2u(const void* p) {
    uint32_t a;
    asm("{ .reg .u64 t; cvta.to.shared.u64 t, %1; cvt.u32.u64 %0, t; }"
        : "=r"(a) : "l"(p));
    return a;
}

__device__ __forceinline__ void cp16(uint32_t dst, const void* src) {
    asm volatile("cp.async.cg.shared.global [%0], [%1], 16;" :: "r"(dst), "l"(src));
}
#define CP_COMMIT() asm volatile("cp.async.commit_group;" ::: "memory")
#define CP_WAIT1()  asm volatile("cp.async.wait_group 1;" ::: "memory")

__device__ __forceinline__ void ldsm4(uint32_t* r, uint32_t addr) {
    asm volatile("ldmatrix.sync.aligned.m8n8.x4.shared.b16 {%0,%1,%2,%3}, [%4];"
        : "=r"(r[0]), "=r"(r[1]), "=r"(r[2]), "=r"(r[3]) : "r"(addr));
}

__device__ __forceinline__ void mma_bf16(float* d, const uint32_t* a, const uint32_t* b) {
    asm volatile(
        "mma.sync.aligned.m16n8k16.row.col.f32.bf16.bf16.f32 "
        "{%0,%1,%2,%3}, {%4,%5,%6,%7}, {%8,%9}, {%0,%1,%2,%3};"
        : "+f"(d[0]), "+f"(d[1]), "+f"(d[2]), "+f"(d[3])
        : "r"(a[0]), "r"(a[1]), "r"(a[2]), "r"(a[3]), "r"(b[0]), "r"(b[1]));
}

__device__ __forceinline__ void mma_f16(float* d, const uint32_t* a, const uint32_t* b) {
    asm volatile(
        "mma.sync.aligned.m16n8k16.row.col.f32.f16.f16.f32 "
        "{%0,%1,%2,%3}, {%4,%5,%6,%7}, {%8,%9}, {%0,%1,%2,%3};"
        : "+f"(d[0]), "+f"(d[1]), "+f"(d[2]), "+f"(d[3])
        : "r"(a[0]), "r"(a[1]), "r"(a[2]), "r"(a[3]), "r"(b[0]), "r"(b[1]));
}

__device__ __forceinline__ uint32_t pack_bf2(float a, float b) {
    __nv_bfloat16 ha = __float2bfloat16(a), hb = __float2bfloat16(b);
    return (uint32_t)__bfloat16_as_ushort(ha) |
           ((uint32_t)__bfloat16_as_ushort(hb) << 16);
}
__device__ __forceinline__ uint32_t pack_h2(float a, float b) {
    __half2 h = __floats2half2_rn(a, b);
    return *(uint32_t*)&h;
}

// ------------------------- tiling constants ---------------------------------
// 128x128x32 block tile, 256 threads, 8 warps (4 M x 2 N), warp tile 32x64.
// smem rows: 64B data + 16B pad = 80B (5x16B, gcd(5,8)=1 -> LDSM conflict-free)
#define ROWB 80
#define TILEB (128 * ROWB)              // 10240 per tile
#define STAGE3 (4 * TILEB)              // 40960 (Ahi,Alo,Bhi,Blo)
#define STAGE1 (2 * TILEB)              // 20480 (A,B)
static constexpr int SMEM3 = 2 * STAGE3;   // 81920  -> 2 CTAs/SM
static constexpr int SMEM1 = 2 * STAGE1;   // 40960  -> 2 CTAs/SM

// ------------------------- stage loaders ------------------------------------
__device__ __forceinline__ void load_stage4(
    uint32_t sbase, const __nv_bfloat16* Ahi, const __nv_bfloat16* Alo,
    const __nv_bfloat16* Bhi, const __nv_bfloat16* Blo,
    int bm0, int bn0, int K, int c, int tid)
{
    const __nv_bfloat16* gp[4] = { Ahi, Alo, Bhi, Blo };
    const int rb[4] = { bm0, bm0, bn0, bn0 };
    const size_t kb = (size_t)c * 32;
#pragma unroll
    for (int t = 0; t < 8; t++) {
        const int seg  = tid + t * 256;
        const int tile = seg >> 9;
        const int w    = seg & 511;
        const int row  = w >> 2;
        const int c16  = w & 3;
        const __nv_bfloat16* src = gp[tile] + (size_t)(rb[tile] + row) * K + kb + c16 * 8;
        cp16(sbase + tile * TILEB + row * ROWB + c16 * 16, src);
    }
}

__device__ __forceinline__ void load_stage2(
    uint32_t sbase, const __half* A, const __half* B,
    int bm0, int bn0, int K, int c, int tid)
{
    const __half* gp[2] = { A, B };
    const int rb[2] = { bm0, bn0 };
    const size_t kb = (size_t)c * 32;
#pragma unroll
    for (int t = 0; t < 4; t++) {
        const int seg  = tid + t * 256;
        const int tile = seg >> 9;
        const int w    = seg & 511;
        const int row  = w >> 2;
        const int c16  = w & 3;
        const __half* src = gp[tile] + (size_t)(rb[tile] + row) * K + kb + c16 * 8;
        cp16(sbase + tile * TILEB + row * ROWB + c16 * 16, src);
    }
}

// ------------------------- 3-term bf16 GEMM kernel --------------------------
// D = Ahi@Bhi^T + Ahi@Blo^T + Alo@Bhi^T
// EPI 0 = SIM (quant->exp -> E fp16 + rowsum atomics), EPI 2 = STORE fp32.
template <int EPI>
__global__ __launch_bounds__(256, 2)
void mma3_kernel(const __nv_bfloat16* __restrict__ Ahi,
                 const __nv_bfloat16* __restrict__ Alo,
                 const __nv_bfloat16* __restrict__ Bhi,
                 const __nv_bfloat16* __restrict__ Blo,
                 int K, int ldC,
                 float* __restrict__ den,
                 __half* __restrict__ E,
                 float* __restrict__ Cf)
{
    extern __shared__ char sm[];
    const uint32_t sb = s2u(sm);
    const int tid  = threadIdx.x;
    const int wid  = tid >> 5;
    const int lane = tid & 31;
    const int wm   = wid >> 1;          // 0..3 (M)
    const int wn   = wid & 1;           // 0..1 (N)
    const int g    = lane >> 2;         // 0..7
    const int tg   = lane & 3;          // 0..3
    const int bm0  = blockIdx.y * 128;
    const int bn0  = blockIdx.x * 128;

    // ldmatrix per-lane address offsets (within a tile)
    const int grp  = lane >> 3;         // 0..3
    const int lrow = lane & 7;
    const uint32_t a_off = (uint32_t)((wm * 32 + lrow + ((grp & 1) << 3)) * ROWB
                                      + ((grp >> 1) << 4));
    const uint32_t b_off = (uint32_t)((wn * 64 + lrow + ((grp >> 1) << 3)) * ROWB
                                      + ((grp & 1) << 4));

    float acc[2][8][4];
#pragma unroll
    for (int mt = 0; mt < 2; mt++)
#pragma unroll
        for (int nt = 0; nt < 8; nt++)
#pragma unroll
            for (int j = 0; j < 4; j++) acc[mt][nt][j] = 0.f;

    const int nch = K >> 5;
    load_stage4(sb,          Ahi, Alo, Bhi, Blo, bm0, bn0, K, 0, tid);
    CP_COMMIT();
    load_stage4(sb + STAGE3, Ahi, Alo, Bhi, Blo, bm0, bn0, K, 1, tid);
    CP_COMMIT();

    for (int c = 0; c < nch; c++) {
        CP_WAIT1();
        __syncthreads();
        const uint32_t st = sb + (c & 1) * STAGE3;

#pragma unroll
        for (int ks = 0; ks < 2; ks++) {
            const uint32_t kk = ks * 32;
            uint32_t ah[2][4], al[2][4];
#pragma unroll
            for (int mt = 0; mt < 2; mt++) {
                ldsm4(ah[mt], st + a_off + mt * (16 * ROWB) + kk);
                ldsm4(al[mt], st + TILEB + a_off + mt * (16 * ROWB) + kk);
            }
#pragma unroll
            for (int np = 0; np < 4; np++) {
                uint32_t bh[4], bl[4];
                ldsm4(bh, st + 2 * TILEB + b_off + np * (16 * ROWB) + kk);
                ldsm4(bl, st + 3 * TILEB + b_off + np * (16 * ROWB) + kk);
#pragma unroll
                for (int sub = 0; sub < 2; sub++) {
                    const int nt = np * 2 + sub;
#pragma unroll
                    for (int mt = 0; mt < 2; mt++) {
                        mma_bf16(acc[mt][nt], ah[mt], &bh[2 * sub]);
                        mma_bf16(acc[mt][nt], ah[mt], &bl[2 * sub]);
                        mma_bf16(acc[mt][nt], al[mt], &bh[2 * sub]);
                    }
                }
            }
        }
        __syncthreads();
        if (c + 2 < nch)
            load_stage4(sb + (c & 1) * STAGE3, Ahi, Alo, Bhi, Blo, bm0, bn0, K, c + 2, tid);
        CP_COMMIT();
    }

    // ------------------------- epilogue -------------------------
    if constexpr (EPI == 0) {          // SIM -> E fp16 + den
        float rs[2][2] = { {0.f, 0.f}, {0.f, 0.f} };
#pragma unroll
        for (int mt = 0; mt < 2; mt++) {
            const int rh = bm0 + wm * 32 + mt * 16 + g;
            const int rl = rh + 8;
#pragma unroll
            for (int nt = 0; nt < 8; nt++) {
                const int col = bn0 + wn * 64 + nt * 8 + tg * 2;
                float e0 = __expf(rintf(acc[mt][nt][0] / 0.05f) * 0.05f);
                float e1 = __expf(rintf(acc[mt][nt][1] / 0.05f) * 0.05f);
                float e2 = __expf(rintf(acc[mt][nt][2] / 0.05f) * 0.05f);
                float e3 = __expf(rintf(acc[mt][nt][3] / 0.05f) * 0.05f);
                rs[mt][0] += e0 + e1;
                rs[mt][1] += e2 + e3;
                *(uint32_t*)(E + (size_t)rh * ldC + col) = pack_h2(e0, e1);
                *(uint32_t*)(E + (size_t)rl * ldC + col) = pack_h2(e2, e3);
            }
        }
#pragma unroll
        for (int mt = 0; mt < 2; mt++)
#pragma unroll
            for (int hl = 0; hl < 2; hl++) {
                float v = rs[mt][hl];
                v += __shfl_xor_sync(0xffffffffu, v, 1);
                v += __shfl_xor_sync(0xffffffffu, v, 2);
                if (tg == 0)
                    atomicAdd(&den[bm0 + wm * 32 + mt * 16 + g + hl * 8], v);
            }
    } else {                           // STORE fp32
#pragma unroll
        for (int mt = 0; mt < 2; mt++) {
            const int rh = bm0 + wm * 32 + mt * 16 + g;
            const int rl = rh + 8;
#pragma unroll
            for (int nt = 0; nt < 8; nt++) {
                const int col = bn0 + wn * 64 + nt * 8 + tg * 2;
                *(float2*)(Cf + (size_t)rh * ldC + col) =
                    make_float2(acc[mt][nt][0], acc[mt][nt][1]);
                *(float2*)(Cf + (size_t)rl * ldC + col) =
                    make_float2(acc[mt][nt][2], acc[mt][nt][3]);
            }
        }
    }
}

// ------------------------- 1-term fp16 OUT kernel ---------------------------
// C = (A @ B^T) / den   (A = E fp16 [M,K], B = Vt fp16 [N,K])
__global__ __launch_bounds__(256, 2)
void out1_kernel(const __half* __restrict__ E,
                 const __half* __restrict__ Vt,
                 int K, int ldC,
                 const float* __restrict__ den,
                 float* __restrict__ Cf)
{
    extern __shared__ char sm[];
    const uint32_t sb = s2u(sm);
    const int tid  = threadIdx.x;
    const int wid  = tid >> 5;
    const int lane = tid & 31;
    const int wm   = wid >> 1;
    const int wn   = wid & 1;
    const int g    = lane >> 2;
    const int tg   = lane & 3;
    const int bm0  = blockIdx.y * 128;
    const int bn0  = blockIdx.x * 128;

    const int grp  = lane >> 3;
    const int lrow = lane & 7;
    const uint32_t a_off = (uint32_t)((wm * 32 + lrow + ((grp & 1) << 3)) * ROWB
                                      + ((grp >> 1) << 4));
    const uint32_t b_off = (uint32_t)((wn * 64 + lrow + ((grp >> 1) << 3)) * ROWB
                                      + ((grp & 1) << 4));

    float acc[2][8][4];
#pragma unroll
    for (int mt = 0; mt < 2; mt++)
#pragma unroll
        for (int nt = 0; nt < 8; nt++)
#pragma unroll
            for (int j = 0; j < 4; j++) acc[mt][nt][j] = 0.f;

    const int nch = K >> 5;
    load_stage2(sb,          E, Vt, bm0, bn0, K, 0, tid);
    CP_COMMIT();
    load_stage2(sb + STAGE1, E, Vt, bm0, bn0, K, 1, tid);
    CP_COMMIT();

    for (int c = 0; c < nch; c++) {
        CP_WAIT1();
        __syncthreads();
        const uint32_t st = sb + (c & 1) * STAGE1;

#pragma unroll
        for (int ks = 0; ks < 2; ks++) {
            const uint32_t kk = ks * 32;
            uint32_t ah[2][4];
#pragma unroll
            for (int mt = 0; mt < 2; mt++)
                ldsm4(ah[mt], st + a_off + mt * (16 * ROWB) + kk);
#pragma unroll
            for (int np = 0; np < 4; np++) {
                uint32_t bh[4];
                ldsm4(bh, st + TILEB + b_off + np * (16 * ROWB) + kk);
#pragma unroll
                for (int sub = 0; sub < 2; sub++) {
                    const int nt = np * 2 + sub;
#pragma unroll
                    for (int mt = 0; mt < 2; mt++)
                        mma_f16(acc[mt][nt], ah[mt], &bh[2 * sub]);
                }
            }
        }
        __syncthreads();
        if (c + 2 < nch)
            load_stage2(sb + (c & 1) * STAGE1, E, Vt, bm0, bn0, K, c + 2, tid);
        CP_COMMIT();
    }

#pragma unroll
    for (int mt = 0; mt < 2; mt++) {
        const int rh = bm0 + wm * 32 + mt * 16 + g;
        const int rl = rh + 8;
        const float sh = 1.0f / den[rh];
        const float sl = 1.0f / den[rl];
#pragma unroll
        for (int nt = 0; nt < 8; nt++) {
            const int col = bn0 + wn * 64 + nt * 8 + tg * 2;
            *(float2*)(Cf + (size_t)rh * ldC + col) =
                make_float2(acc[mt][nt][0] * sh, acc[mt][nt][1] * sh);
            *(float2*)(Cf + (size_t)rl * ldC + col) =
                make_float2(acc[mt][nt][2] * sl, acc[mt][nt][3] * sl);
        }
    }
}

// ------------------------- split fp32 -> bf16 hi/lo -------------------------
__global__ void split_kernel(const float* __restrict__ s,
                             __nv_bfloat16* __restrict__ hi,
                             __nv_bfloat16* __restrict__ lo, int n4)
{
    const int i = blockIdx.x * blockDim.x + threadIdx.x;
    if (i >= n4) return;
    float4 v = ((const float4*)s)[i];
    const float f[4] = { v.x, v.y, v.z, v.w };
    uint32_t hp[2], lp[2];
#pragma unroll
    for (int j = 0; j < 2; j++) {
        __nv_bfloat16 h0 = __float2bfloat16(f[2 * j]);
        __nv_bfloat16 h1 = __float2bfloat16(f[2 * j + 1]);
        hp[j] = (uint32_t)__bfloat16_as_ushort(h0) |
                ((uint32_t)__bfloat16_as_ushort(h1) << 16);
        lp[j] = pack_bf2(f[2 * j]     - __bfloat162float(h0),
                         f[2 * j + 1] - __bfloat162float(h1));
    }
    *(uint2*)(hi + (size_t)i * 4) = make_uint2(hp[0], hp[1]);
    *(uint2*)(lo + (size_t)i * 4) = make_uint2(lp[0], lp[1]);
}

// ----------------- transpose + split: src[R,C] -> out[C,R] bf16 hi/lo -------
__global__ void trans_split_kernel(const float* __restrict__ src,
                                   __nv_bfloat16* __restrict__ hi,
                                   __nv_bfloat16* __restrict__ lo,
                                   int R, int C)
{
    __shared__ float t[32][33];
    const int c0 = blockIdx.x * 32, r0 = blockIdx.y * 32;
    const int tx = threadIdx.x, ty = threadIdx.y;   // 32 x 8
#pragma unroll
    for (int j = 0; j < 32; j += 8)
        t[ty + j][tx] = src[(size_t)(r0 + ty + j) * C + c0 + tx];
    __syncthreads();
#pragma unroll
    for (int j = 0; j < 32; j += 8) {
        const float v = t[tx][ty + j];
        __nv_bfloat16 h = __float2bfloat16(v);
        const size_t o = (size_t)(c0 + ty + j) * R + r0 + tx;
        hi[o] = h;
        lo[o] = __float2bfloat16(v - __bfloat162float(h));
    }
}

// ----------------- transpose: src[R,C] fp32 -> out[C,R] fp16 ----------------
__global__ void trans_half_kernel(const float* __restrict__ src,
                                  __half* __restrict__ dst,
                                  int R, int C)
{
    __shared__ float t[32][33];
    const int c0 = blockIdx.x * 32, r0 = blockIdx.y * 32;
    const int tx = threadIdx.x, ty = threadIdx.y;   // 32 x 8
#pragma unroll
    for (int j = 0; j < 32; j += 8)
        t[ty + j][tx] = src[(size_t)(r0 + ty + j) * C + c0 + tx];
    __syncthreads();
#pragma unroll
    for (int j = 0; j < 32; j += 8)
        dst[(size_t)(c0 + ty + j) * R + r0 + tx] = __float2half_rn(t[tx][ty + j]);
}

// ------------------------- l2 normalize + split -----------------------------
__global__ void l2norm_split_kernel(const float* __restrict__ P,
                                    __nv_bfloat16* __restrict__ hi,
                                    __nv_bfloat16* __restrict__ lo)
{
    const int r = blockIdx.x;
    const int t = threadIdx.x;  // 128 threads x float4 (H=512)
    const float4 v = ((const float4*)(P + (size_t)r * 512))[t];
    float ss = v.x * v.x + v.y * v.y + v.z * v.z + v.w * v.w;
#pragma unroll
    for (int m = 16; m; m >>= 1) ss += __shfl_xor_sync(0xffffffffu, ss, m);
    __shared__ float ws[4];
    if ((t & 31) == 0) ws[t >> 5] = ss;
    __syncthreads();
    const float d = fmaxf(sqrtf(ws[0] + ws[1] + ws[2] + ws[3]), 1e-12f);
    const float f[4] = { v.x / d, v.y / d, v.z / d, v.w / d };
    uint32_t hp[2], lp[2];
#pragma unroll
    for (int j = 0; j < 2; j++) {
        __nv_bfloat16 h0 = __float2bfloat16(f[2 * j]);
        __nv_bfloat16 h1 = __float2bfloat16(f[2 * j + 1]);
        hp[j] = (uint32_t)__bfloat16_as_ushort(h0) |
                ((uint32_t)__bfloat16_as_ushort(h1) << 16);
        lp[j] = pack_bf2(f[2 * j]     - __bfloat162float(h0),
                         f[2 * j + 1] - __bfloat162float(h1));
    }
    const size_t off = (size_t)r * 512 + t * 4;
    *(uint2*)(hi + off) = make_uint2(hp[0], hp[1]);
    *(uint2*)(lo + off) = make_uint2(lp[0], lp[1]);
}

__global__ void zero_kernel(float* __restrict__ p, int n)
{
    const int i = blockIdx.x * blockDim.x + threadIdx.x;
    if (i < n) p[i] = 0.f;
}

// ------------------------- launch -------------------------------------------
extern "C" void kernel_launch(void* const* d_in, const int* in_sizes, int n_in,
                              void* d_out, int out_size)
{
    const float* x       = (const float*)d_in[0];
    const float* anchors = (const float*)d_in[1];
    const float* Wq      = (const float*)d_in[2];
    const float* Wk      = (const float*)d_in[3];
    const float* values  = (const float*)d_in[4];
    float* out = (float*)d_out;

    const int D = 512, H = 512;
    const int B = in_sizes[0] / D;   // 16384
    const int A = in_sizes[1] / D;   // 4096

    float *Qf, *Kf, *dn;
    __nv_bfloat16 *xhi, *xlo, *ahi, *alo, *Wqthi, *Wqtlo, *Wkthi, *Wktlo;
    __nv_bfloat16 *Qhi, *Qlo, *Khi, *Klo;
    __half *E, *Vt;
    cudaGetSymbolAddress((void**)&Qf,    g_Qf);
    cudaGetSymbolAddress((void**)&Kf,    g_Kf);
    cudaGetSymbolAddress((void**)&dn,    g_den);
    cudaGetSymbolAddress((void**)&xhi,   g_xhi);
    cudaGetSymbolAddress((void**)&xlo,   g_xlo);
    cudaGetSymbolAddress((void**)&ahi,   g_ahi);
    cudaGetSymbolAddress((void**)&alo,   g_alo);
    cudaGetSymbolAddress((void**)&Wqthi, g_Wqthi);
    cudaGetSymbolAddress((void**)&Wqtlo, g_Wqtlo);
    cudaGetSymbolAddress((void**)&Wkthi, g_Wkthi);
    cudaGetSymbolAddress((void**)&Wktlo, g_Wktlo);
    cudaGetSymbolAddress((void**)&Qhi,   g_Qhi);
    cudaGetSymbolAddress((void**)&Qlo,   g_Qlo);
    cudaGetSymbolAddress((void**)&Khi,   g_Khi);
    cudaGetSymbolAddress((void**)&Klo,   g_Klo);
    cudaGetSymbolAddress((void**)&E,     g_E);
    cudaGetSymbolAddress((void**)&Vt,    g_Vt);

    cudaFuncSetAttribute(mma3_kernel<0>,
                         cudaFuncAttributeMaxDynamicSharedMemorySize, SMEM3);
    cudaFuncSetAttribute(mma3_kernel<2>,
                         cudaFuncAttributeMaxDynamicSharedMemorySize, SMEM3);
    cudaFuncSetAttribute(out1_kernel,
                         cudaFuncAttributeMaxDynamicSharedMemorySize, SMEM1);

    // 1) splits / transposes
    split_kernel<<<(B * D / 4 + 255) / 256, 256>>>(x, xhi, xlo, B * D / 4);
    split_kernel<<<(A * D / 4 + 255) / 256, 256>>>(anchors, ahi, alo, A * D / 4);
    trans_split_kernel<<<dim3(H / 32, D / 32), dim3(32, 8)>>>(Wq, Wqthi, Wqtlo, D, H);
    trans_split_kernel<<<dim3(H / 32, D / 32), dim3(32, 8)>>>(Wk, Wkthi, Wktlo, D, H);
    trans_half_kernel<<<dim3(H / 32, A / 32), dim3(32, 8)>>>(values, Vt, A, H);

    // 2) projections (3-term bf16 mma, fp32 store)
    mma3_kernel<2><<<dim3(H / 128, B / 128), 256, SMEM3>>>(
        xhi, xlo, Wqthi, Wqtlo, D, H, nullptr, nullptr, Qf);
    mma3_kernel<2><<<dim3(H / 128, A / 128), 256, SMEM3>>>(
        ahi, alo, Wkthi, Wktlo, D, H, nullptr, nullptr, Kf);

    // 3) l2 normalize + split
    l2norm_split_kernel<<<B, 128>>>(Qf, Qhi, Qlo);
    l2norm_split_kernel<<<A, 128>>>(Kf, Khi, Klo);

    // 4) zero den
    zero_kernel<<<(B + 255) / 256, 256>>>(dn, B);

    // 5) SIM: E = exp(quant(Qn @ Kn^T)) fp16, den = rowsum
    mma3_kernel<0><<<dim3(A / 128, B / 128), 256, SMEM3>>>(
        Qhi, Qlo, Khi, Klo, H, A, dn, E, nullptr);

    // 6) OUT: out = (E @ V) / den  (1-term fp16)
    out1_kernel<<<dim3(H / 128, B / 128), 256, SMEM1>>>(
        E, Vt, A, H, dn, out);
}

// round 8
// speedup vs baseline: 3.7952x; 1.0063x over previous
#include <cuda_runtime.h>
#include <cuda_bf16.h>
#include <cuda_fp16.h>
#include <cstdint>
#include <cstddef>

// ===========================================================================
// RelativeAttention on sm_100 (plain target: legacy mma.sync / HMMA).
// R8: batched LDSM fragment loads + term-major (dependency-free) MMA issue.
//
//   1) split x, anchors -> bf16 hi/lo; transpose+split Wq, Wk; values -> Vt fp16
//   2) Qf = x @ Wq, Kf = anchors @ Wk    (3-term bf16 mma, fp32 store)
//   3) l2norm rows + split -> Q/K bf16 hi/lo
//   4) zero den
//   5) SIM (3-term bf16): quant->exp -> E fp16 + rowsum atomics
//   6) OUT (1-term fp16): O = E @ Vt^T -> scale 1/den -> fp32 out
// ===========================================================================

// ------------------------- device scratch ----------------------------------
__device__ float g_Qf[16384 * 512];
__device__ float g_Kf[4096 * 512];
__device__ float g_den[16384];
__device__ __nv_bfloat16 g_xhi[16384 * 512];
__device__ __nv_bfloat16 g_xlo[16384 * 512];
__device__ __nv_bfloat16 g_ahi[4096 * 512];
__device__ __nv_bfloat16 g_alo[4096 * 512];
__device__ __nv_bfloat16 g_Wqthi[512 * 512];
__device__ __nv_bfloat16 g_Wqtlo[512 * 512];
__device__ __nv_bfloat16 g_Wkthi[512 * 512];
__device__ __nv_bfloat16 g_Wktlo[512 * 512];
__device__ __nv_bfloat16 g_Qhi[16384 * 512];
__device__ __nv_bfloat16 g_Qlo[16384 * 512];
__device__ __nv_bfloat16 g_Khi[4096 * 512];
__device__ __nv_bfloat16 g_Klo[4096 * 512];
__device__ __half g_E[(size_t)16384 * 4096];
__device__ __half g_Vt[512 * 4096];

// ------------------------- helpers -----------------------------------------
__device__ __forceinline__ uint32_t s2u(const void* p) {
    uint32_t a;
    asm("{ .reg .u64 t; cvta.to.shared.u64 t, %1; cvt.u32.u64 %0, t; }"
        : "=r"(a) : "l"(p));
    return a;
}

__device__ __forceinline__ void cp16(uint32_t dst, const void* src) {
    asm volatile("cp.async.cg.shared.global [%0], [%1], 16;" :: "r"(dst), "l"(src));
}
#define CP_COMMIT() asm volatile("cp.async.commit_group;" ::: "memory")
#define CP_WAIT1()  asm volatile("cp.async.wait_group 1;" ::: "memory")

__device__ __forceinline__ void ldsm4(uint32_t* r, uint32_t addr) {
    asm volatile("ldmatrix.sync.aligned.m8n8.x4.shared.b16 {%0,%1,%2,%3}, [%4];"
        : "=r"(r[0]), "=r"(r[1]), "=r"(r[2]), "=r"(r[3]) : "r"(addr));
}

__device__ __forceinline__ void mma_bf16(float* d, const uint32_t* a, const uint32_t* b) {
    asm volatile(
        "mma.sync.aligned.m16n8k16.row.col.f32.bf16.bf16.f32 "
        "{%0,%1,%2,%3}, {%4,%5,%6,%7}, {%8,%9}, {%0,%1,%2,%3};"
        : "+f"(d[0]), "+f"(d[1]), "+f"(d[2]), "+f"(d[3])
        : "r"(a[0]), "r"(a[1]), "r"(a[2]), "r"(a[3]), "r"(b[0]), "r"(b[1]));
}

__device__ __forceinline__ void mma_f16(float* d, const uint32_t* a, const uint32_t* b) {
    asm volatile(
        "mma.sync.aligned.m16n8k16.row.col.f32.f16.f16.f32 "
        "{%0,%1,%2,%3}, {%4,%5,%6,%7}, {%8,%9}, {%0,%1,%2,%3};"
        : "+f"(d[0]), "+f"(d[1]), "+f"(d[2]), "+f"(d[3])
        : "r"(a[0]), "r"(a[1]), "r"(a[2]), "r"(a[3]), "r"(b[0]), "r"(b[1]));
}

__device__ __forceinline__ uint32_t pack_bf2(float a, float b) {
    __nv_bfloat16 ha = __float2bfloat16(a), hb = __float2bfloat16(b);
    return (uint32_t)__bfloat16_as_ushort(ha) |
           ((uint32_t)__bfloat16_as_ushort(hb) << 16);
}
__device__ __forceinline__ uint32_t pack_h2(float a, float b) {
    __half2 h = __floats2half2_rn(a, b);
    return *(uint32_t*)&h;
}

// ------------------------- tiling constants ---------------------------------
// 128x128x32 block tile, 256 threads, 8 warps (4 M x 2 N), warp tile 32x64.
// smem rows: 64B data + 16B pad = 80B (5x16B, gcd(5,8)=1 -> LDSM conflict-free)
#define ROWB 80
#define TILEB (128 * ROWB)              // 10240 per tile
#define STAGE3 (4 * TILEB)              // 40960 (Ahi,Alo,Bhi,Blo)
#define STAGE1 (2 * TILEB)              // 20480 (A,B)
static constexpr int SMEM3 = 2 * STAGE3;   // 81920  -> 2 CTAs/SM
static constexpr int SMEM1 = 2 * STAGE1;   // 40960  -> 2 CTAs/SM

// ------------------------- stage loaders ------------------------------------
__device__ __forceinline__ void load_stage4(
    uint32_t sbase, const __nv_bfloat16* Ahi, const __nv_bfloat16* Alo,
    const __nv_bfloat16* Bhi, const __nv_bfloat16* Blo,
    int bm0, int bn0, int K, int c, int tid)
{
    const __nv_bfloat16* gp[4] = { Ahi, Alo, Bhi, Blo };
    const int rb[4] = { bm0, bm0, bn0, bn0 };
    const size_t kb = (size_t)c * 32;
#pragma unroll
    for (int t = 0; t < 8; t++) {
        const int seg  = tid + t * 256;
        const int tile = seg >> 9;
        const int w    = seg & 511;
        const int row  = w >> 2;
        const int c16  = w & 3;
        const __nv_bfloat16* src = gp[tile] + (size_t)(rb[tile] + row) * K + kb + c16 * 8;
        cp16(sbase + tile * TILEB + row * ROWB + c16 * 16, src);
    }
}

__device__ __forceinline__ void load_stage2(
    uint32_t sbase, const __half* A, const __half* B,
    int bm0, int bn0, int K, int c, int tid)
{
    const __half* gp[2] = { A, B };
    const int rb[2] = { bm0, bn0 };
    const size_t kb = (size_t)c * 32;
#pragma unroll
    for (int t = 0; t < 4; t++) {
        const int seg  = tid + t * 256;
        const int tile = seg >> 9;
        const int w    = seg & 511;
        const int row  = w >> 2;
        const int c16  = w & 3;
        const __half* src = gp[tile] + (size_t)(rb[tile] + row) * K + kb + c16 * 8;
        cp16(sbase + tile * TILEB + row * ROWB + c16 * 16, src);
    }
}

// ------------------------- 3-term bf16 GEMM kernel --------------------------
// D = Ahi@Bhi^T + Ahi@Blo^T + Alo@Bhi^T
// EPI 0 = SIM (quant->exp -> E fp16 + rowsum atomics), EPI 2 = STORE fp32.
template <int EPI>
__global__ __launch_bounds__(256, 2)
void mma3_kernel(const __nv_bfloat16* __restrict__ Ahi,
                 const __nv_bfloat16* __restrict__ Alo,
                 const __nv_bfloat16* __restrict__ Bhi,
                 const __nv_bfloat16* __restrict__ Blo,
                 int K, int ldC,
                 float* __restrict__ den,
                 __half* __restrict__ E,
                 float* __restrict__ Cf)
{
    extern __shared__ char sm[];
    const uint32_t sb = s2u(sm);
    const int tid  = threadIdx.x;
    const int wid  = tid >> 5;
    const int lane = tid & 31;
    const int wm   = wid >> 1;          // 0..3 (M)
    const int wn   = wid & 1;           // 0..1 (N)
    const int g    = lane >> 2;         // 0..7
    const int tg   = lane & 3;          // 0..3
    const int bm0  = blockIdx.y * 128;
    const int bn0  = blockIdx.x * 128;

    // ldmatrix per-lane address offsets (within a tile)
    const int grp  = lane >> 3;         // 0..3
    const int lrow = lane & 7;
    const uint32_t a_off = (uint32_t)((wm * 32 + lrow + ((grp & 1) << 3)) * ROWB
                                      + ((grp >> 1) << 4));
    const uint32_t b_off = (uint32_t)((wn * 64 + lrow + ((grp >> 1) << 3)) * ROWB
                                      + ((grp & 1) << 4));

    float acc[2][8][4];
#pragma unroll
    for (int mt = 0; mt < 2; mt++)
#pragma unroll
        for (int nt = 0; nt < 8; nt++)
#pragma unroll
            for (int j = 0; j < 4; j++) acc[mt][nt][j] = 0.f;

    const int nch = K >> 5;
    load_stage4(sb,          Ahi, Alo, Bhi, Blo, bm0, bn0, K, 0, tid);
    CP_COMMIT();
    load_stage4(sb + STAGE3, Ahi, Alo, Bhi, Blo, bm0, bn0, K, 1, tid);
    CP_COMMIT();

    for (int c = 0; c < nch; c++) {
        CP_WAIT1();
        __syncthreads();
        const uint32_t st = sb + (c & 1) * STAGE3;

#pragma unroll
        for (int ks = 0; ks < 2; ks++) {
            const uint32_t kk = ks * 32;
            // ---- batch ALL fragment loads (12 x LDSM.x4, high MLP) ----
            uint32_t ah[2][4], al[2][4], bh[4][4], bl[4][4];
#pragma unroll
            for (int mt = 0; mt < 2; mt++)
                ldsm4(ah[mt], st + a_off + mt * (16 * ROWB) + kk);
#pragma unroll
            for (int mt = 0; mt < 2; mt++)
                ldsm4(al[mt], st + TILEB + a_off + mt * (16 * ROWB) + kk);
#pragma unroll
            for (int np = 0; np < 4; np++)
                ldsm4(bh[np], st + 2 * TILEB + b_off + np * (16 * ROWB) + kk);
#pragma unroll
            for (int np = 0; np < 4; np++)
                ldsm4(bl[np], st + 3 * TILEB + b_off + np * (16 * ROWB) + kk);
            // ---- term-major MMA: 3 runs of 16 independent accumulators ----
#pragma unroll
            for (int np = 0; np < 4; np++)
#pragma unroll
                for (int sub = 0; sub < 2; sub++)
#pragma unroll
                    for (int mt = 0; mt < 2; mt++)
                        mma_bf16(acc[mt][np * 2 + sub], ah[mt], &bh[np][2 * sub]);
#pragma unroll
            for (int np = 0; np < 4; np++)
#pragma unroll
                for (int sub = 0; sub < 2; sub++)
#pragma unroll
                    for (int mt = 0; mt < 2; mt++)
                        mma_bf16(acc[mt][np * 2 + sub], ah[mt], &bl[np][2 * sub]);
#pragma unroll
            for (int np = 0; np < 4; np++)
#pragma unroll
                for (int sub = 0; sub < 2; sub++)
#pragma unroll
                    for (int mt = 0; mt < 2; mt++)
                        mma_bf16(acc[mt][np * 2 + sub], al[mt], &bh[np][2 * sub]);
        }
        __syncthreads();
        if (c + 2 < nch)
            load_stage4(sb + (c & 1) * STAGE3, Ahi, Alo, Bhi, Blo, bm0, bn0, K, c + 2, tid);
        CP_COMMIT();
    }

    // ------------------------- epilogue -------------------------
    if constexpr (EPI == 0) {          // SIM -> E fp16 + den
        float rs[2][2] = { {0.f, 0.f}, {0.f, 0.f} };
#pragma unroll
        for (int mt = 0; mt < 2; mt++) {
            const int rh = bm0 + wm * 32 + mt * 16 + g;
            const int rl = rh + 8;
#pragma unroll
            for (int nt = 0; nt < 8; nt++) {
                const int col = bn0 + wn * 64 + nt * 8 + tg * 2;
                float e0 = __expf(rintf(acc[mt][nt][0] / 0.05f) * 0.05f);
                float e1 = __expf(rintf(acc[mt][nt][1] / 0.05f) * 0.05f);
                float e2 = __expf(rintf(acc[mt][nt][2] / 0.05f) * 0.05f);
                float e3 = __expf(rintf(acc[mt][nt][3] / 0.05f) * 0.05f);
                rs[mt][0] += e0 + e1;
                rs[mt][1] += e2 + e3;
                *(uint32_t*)(E + (size_t)rh * ldC + col) = pack_h2(e0, e1);
                *(uint32_t*)(E + (size_t)rl * ldC + col) = pack_h2(e2, e3);
            }
        }
#pragma unroll
        for (int mt = 0; mt < 2; mt++)
#pragma unroll
            for (int hl = 0; hl < 2; hl++) {
                float v = rs[mt][hl];
                v += __shfl_xor_sync(0xffffffffu, v, 1);
                v += __shfl_xor_sync(0xffffffffu, v, 2);
                if (tg == 0)
                    atomicAdd(&den[bm0 + wm * 32 + mt * 16 + g + hl * 8], v);
            }
    } else {                           // STORE fp32
#pragma unroll
        for (int mt = 0; mt < 2; mt++) {
            const int rh = bm0 + wm * 32 + mt * 16 + g;
            const int rl = rh + 8;
#pragma unroll
            for (int nt = 0; nt < 8; nt++) {
                const int col = bn0 + wn * 64 + nt * 8 + tg * 2;
                *(float2*)(Cf + (size_t)rh * ldC + col) =
                    make_float2(acc[mt][nt][0], acc[mt][nt][1]);
                *(float2*)(Cf + (size_t)rl * ldC + col) =
                    make_float2(acc[mt][nt][2], acc[mt][nt][3]);
            }
        }
    }
}

// ------------------------- 1-term fp16 OUT kernel ---------------------------
// C = (A @ B^T) / den   (A = E fp16 [M,K], B = Vt fp16 [N,K])
__global__ __launch_bounds__(256, 2)
void out1_kernel(const __half* __restrict__ E,
                 const __half* __restrict__ Vt,
                 int K, int ldC,
                 const float* __restrict__ den,
                 float* __restrict__ Cf)
{
    extern __shared__ char sm[];
    const uint32_t sb = s2u(sm);
    const int tid  = threadIdx.x;
    const int wid  = tid >> 5;
    const int lane = tid & 31;
    const int wm   = wid >> 1;
    const int wn   = wid & 1;
    const int g    = lane >> 2;
    const int tg   = lane & 3;
    const int bm0  = blockIdx.y * 128;
    const int bn0  = blockIdx.x * 128;

    const int grp  = lane >> 3;
    const int lrow = lane & 7;
    const uint32_t a_off = (uint32_t)((wm * 32 + lrow + ((grp & 1) << 3)) * ROWB
                                      + ((grp >> 1) << 4));
    const uint32_t b_off = (uint32_t)((wn * 64 + lrow + ((grp >> 1) << 3)) * ROWB
                                      + ((grp & 1) << 4));

    float acc[2][8][4];
#pragma unroll
    for (int mt = 0; mt < 2; mt++)
#pragma unroll
        for (int nt = 0; nt < 8; nt++)
#pragma unroll
            for (int j = 0; j < 4; j++) acc[mt][nt][j] = 0.f;

    const int nch = K >> 5;
    load_stage2(sb,          E, Vt, bm0, bn0, K, 0, tid);
    CP_COMMIT();
    load_stage2(sb + STAGE1, E, Vt, bm0, bn0, K, 1, tid);
    CP_COMMIT();

    for (int c = 0; c < nch; c++) {
        CP_WAIT1();
        __syncthreads();
        const uint32_t st = sb + (c & 1) * STAGE1;

#pragma unroll
        for (int ks = 0; ks < 2; ks++) {
            const uint32_t kk = ks * 32;
            // ---- batch fragment loads (6 x LDSM.x4) ----
            uint32_t ah[2][4], bh[4][4];
#pragma unroll
            for (int mt = 0; mt < 2; mt++)
                ldsm4(ah[mt], st + a_off + mt * (16 * ROWB) + kk);
#pragma unroll
            for (int np = 0; np < 4; np++)
                ldsm4(bh[np], st + TILEB + b_off + np * (16 * ROWB) + kk);
            // ---- 16 independent MMAs ----
#pragma unroll
            for (int np = 0; np < 4; np++)
#pragma unroll
                for (int sub = 0; sub < 2; sub++)
#pragma unroll
                    for (int mt = 0; mt < 2; mt++)
                        mma_f16(acc[mt][np * 2 + sub], ah[mt], &bh[np][2 * sub]);
        }
        __syncthreads();
        if (c + 2 < nch)
            load_stage2(sb + (c & 1) * STAGE1, E, Vt, bm0, bn0, K, c + 2, tid);
        CP_COMMIT();
    }

#pragma unroll
    for (int mt = 0; mt < 2; mt++) {
        const int rh = bm0 + wm * 32 + mt * 16 + g;
        const int rl = rh + 8;
        const float sh = 1.0f / den[rh];
        const float sl = 1.0f / den[rl];
#pragma unroll
        for (int nt = 0; nt < 8; nt++) {
            const int col = bn0 + wn * 64 + nt * 8 + tg * 2;
            *(float2*)(Cf + (size_t)rh * ldC + col) =
                make_float2(acc[mt][nt][0] * sh, acc[mt][nt][1] * sh);
            *(float2*)(Cf + (size_t)rl * ldC + col) =
                make_float2(acc[mt][nt][2] * sl, acc[mt][nt][3] * sl);
        }
    }
}

// ------------------------- split fp32 -> bf16 hi/lo -------------------------
__global__ void split_kernel(const float* __restrict__ s,
                             __nv_bfloat16* __restrict__ hi,
                             __nv_bfloat16* __restrict__ lo, int n4)
{
    const int i = blockIdx.x * blockDim.x + threadIdx.x;
    if (i >= n4) return;
    float4 v = ((const float4*)s)[i];
    const float f[4] = { v.x, v.y, v.z, v.w };
    uint32_t hp[2], lp[2];
#pragma unroll
    for (int j = 0; j < 2; j++) {
        __nv_bfloat16 h0 = __float2bfloat16(f[2 * j]);
        __nv_bfloat16 h1 = __float2bfloat16(f[2 * j + 1]);
        hp[j] = (uint32_t)__bfloat16_as_ushort(h0) |
                ((uint32_t)__bfloat16_as_ushort(h1) << 16);
        lp[j] = pack_bf2(f[2 * j]     - __bfloat162float(h0),
                         f[2 * j + 1] - __bfloat162float(h1));
    }
    *(uint2*)(hi + (size_t)i * 4) = make_uint2(hp[0], hp[1]);
    *(uint2*)(lo + (size_t)i * 4) = make_uint2(lp[0], lp[1]);
}

// ----------------- transpose + split: src[R,C] -> out[C,R] bf16 hi/lo -------
__global__ void trans_split_kernel(const float* __restrict__ src,
                                   __nv_bfloat16* __restrict__ hi,
                                   __nv_bfloat16* __restrict__ lo,
                                   int R, int C)
{
    __shared__ float t[32][33];
    const int c0 = blockIdx.x * 32, r0 = blockIdx.y * 32;
    const int tx = threadIdx.x, ty = threadIdx.y;   // 32 x 8
#pragma unroll
    for (int j = 0; j < 32; j += 8)
        t[ty + j][tx] = src[(size_t)(r0 + ty + j) * C + c0 + tx];
    __syncthreads();
#pragma unroll
    for (int j = 0; j < 32; j += 8) {
        const float v = t[tx][ty + j];
        __nv_bfloat16 h = __float2bfloat16(v);
        const size_t o = (size_t)(c0 + ty + j) * R + r0 + tx;
        hi[o] = h;
        lo[o] = __float2bfloat16(v - __bfloat162float(h));
    }
}

// ----------------- transpose: src[R,C] fp32 -> out[C,R] fp16 ----------------
__global__ void trans_half_kernel(const float* __restrict__ src,
                                  __half* __restrict__ dst,
                                  int R, int C)
{
    __shared__ float t[32][33];
    const int c0 = blockIdx.x * 32, r0 = blockIdx.y * 32;
    const int tx = threadIdx.x, ty = threadIdx.y;   // 32 x 8
#pragma unroll
    for (int j = 0; j < 32; j += 8)
        t[ty + j][tx] = src[(size_t)(r0 + ty + j) * C + c0 + tx];
    __syncthreads();
#pragma unroll
    for (int j = 0; j < 32; j += 8)
        dst[(size_t)(c0 + ty + j) * R + r0 + tx] = __float2half_rn(t[tx][ty + j]);
}

// ------------------------- l2 normalize + split -----------------------------
__global__ void l2norm_split_kernel(const float* __restrict__ P,
                                    __nv_bfloat16* __restrict__ hi,
                                    __nv_bfloat16* __restrict__ lo)
{
    const int r = blockIdx.x;
    const int t = threadIdx.x;  // 128 threads x float4 (H=512)
    const float4 v = ((const float4*)(P + (size_t)r * 512))[t];
    float ss = v.x * v.x + v.y * v.y + v.z * v.z + v.w * v.w;
#pragma unroll
    for (int m = 16; m; m >>= 1) ss += __shfl_xor_sync(0xffffffffu, ss, m);
    __shared__ float ws[4];
    if ((t & 31) == 0) ws[t >> 5] = ss;
    __syncthreads();
    const float d = fmaxf(sqrtf(ws[0] + ws[1] + ws[2] + ws[3]), 1e-12f);
    const float f[4] = { v.x / d, v.y / d, v.z / d, v.w / d };
    uint32_t hp[2], lp[2];
#pragma unroll
    for (int j = 0; j < 2; j++) {
        __nv_bfloat16 h0 = __float2bfloat16(f[2 * j]);
        __nv_bfloat16 h1 = __float2bfloat16(f[2 * j + 1]);
        hp[j] = (uint32_t)__bfloat16_as_ushort(h0) |
                ((uint32_t)__bfloat16_as_ushort(h1) << 16);
        lp[j] = pack_bf2(f[2 * j]     - __bfloat162float(h0),
                         f[2 * j + 1] - __bfloat162float(h1));
    }
    const size_t off = (size_t)r * 512 + t * 4;
    *(uint2*)(hi + off) = make_uint2(hp[0], hp[1]);
    *(uint2*)(lo + off) = make_uint2(lp[0], lp[1]);
}

__global__ void zero_kernel(float* __restrict__ p, int n)
{
    const int i = blockIdx.x * blockDim.x + threadIdx.x;
    if (i < n) p[i] = 0.f;
}

// ------------------------- launch -------------------------------------------
extern "C" void kernel_launch(void* const* d_in, const int* in_sizes, int n_in,
                              void* d_out, int out_size)
{
    const float* x       = (const float*)d_in[0];
    const float* anchors = (const float*)d_in[1];
    const float* Wq      = (const float*)d_in[2];
    const float* Wk      = (const float*)d_in[3];
    const float* values  = (const float*)d_in[4];
    float* out = (float*)d_out;

    const int D = 512, H = 512;
    const int B = in_sizes[0] / D;   // 16384
    const int A = in_sizes[1] / D;   // 4096

    float *Qf, *Kf, *dn;
    __nv_bfloat16 *xhi, *xlo, *ahi, *alo, *Wqthi, *Wqtlo, *Wkthi, *Wktlo;
    __nv_bfloat16 *Qhi, *Qlo, *Khi, *Klo;
    __half *E, *Vt;
    cudaGetSymbolAddress((void**)&Qf,    g_Qf);
    cudaGetSymbolAddress((void**)&Kf,    g_Kf);
    cudaGetSymbolAddress((void**)&dn,    g_den);
    cudaGetSymbolAddress((void**)&xhi,   g_xhi);
    cudaGetSymbolAddress((void**)&xlo,   g_xlo);
    cudaGetSymbolAddress((void**)&ahi,   g_ahi);
    cudaGetSymbolAddress((void**)&alo,   g_alo);
    cudaGetSymbolAddress((void**)&Wqthi, g_Wqthi);
    cudaGetSymbolAddress((void**)&Wqtlo, g_Wqtlo);
    cudaGetSymbolAddress((void**)&Wkthi, g_Wkthi);
    cudaGetSymbolAddress((void**)&Wktlo, g_Wktlo);
    cudaGetSymbolAddress((void**)&Qhi,   g_Qhi);
    cudaGetSymbolAddress((void**)&Qlo,   g_Qlo);
    cudaGetSymbolAddress((void**)&Khi,   g_Khi);
    cudaGetSymbolAddress((void**)&Klo,   g_Klo);
    cudaGetSymbolAddress((void**)&E,     g_E);
    cudaGetSymbolAddress((void**)&Vt,    g_Vt);

    cudaFuncSetAttribute(mma3_kernel<0>,
                         cudaFuncAttributeMaxDynamicSharedMemorySize, SMEM3);
    cudaFuncSetAttribute(mma3_kernel<2>,
                         cudaFuncAttributeMaxDynamicSharedMemorySize, SMEM3);
    cudaFuncSetAttribute(out1_kernel,
                         cudaFuncAttributeMaxDynamicSharedMemorySize, SMEM1);

    // 1) splits / transposes
    split_kernel<<<(B * D / 4 + 255) / 256, 256>>>(x, xhi, xlo, B * D / 4);
    split_kernel<<<(A * D / 4 + 255) / 256, 256>>>(anchors, ahi, alo, A * D / 4);
    trans_split_kernel<<<dim3(H / 32, D / 32), dim3(32, 8)>>>(Wq, Wqthi, Wqtlo, D, H);
    trans_split_kernel<<<dim3(H / 32, D / 32), dim3(32, 8)>>>(Wk, Wkthi, Wktlo, D, H);
    trans_half_kernel<<<dim3(H / 32, A / 32), dim3(32, 8)>>>(values, Vt, A, H);

    // 2) projections (3-term bf16 mma, fp32 store)
    mma3_kernel<2><<<dim3(H / 128, B / 128), 256, SMEM3>>>(
        xhi, xlo, Wqthi, Wqtlo, D, H, nullptr, nullptr, Qf);
    mma3_kernel<2><<<dim3(H / 128, A / 128), 256, SMEM3>>>(
        ahi, alo, Wkthi, Wktlo, D, H, nullptr, nullptr, Kf);

    // 3) l2 normalize + split
    l2norm_split_kernel<<<B, 128>>>(Qf, Qhi, Qlo);
    l2norm_split_kernel<<<A, 128>>>(Kf, Khi, Klo);

    // 4) zero den
    zero_kernel<<<(B + 255) / 256, 256>>>(dn, B);

    // 5) SIM: E = exp(quant(Qn @ Kn^T)) fp16, den = rowsum
    mma3_kernel<0><<<dim3(A / 128, B / 128), 256, SMEM3>>>(
        Qhi, Qlo, Khi, Klo, H, A, dn, E, nullptr);

    // 6) OUT: out = (E @ V) / den  (1-term fp16)
    out1_kernel<<<dim3(H / 128, B / 128), 256, SMEM1>>>(
        E, Vt, A, H, dn, out);
}

// round 9
// speedup vs baseline: 4.5082x; 1.1879x over previous
#include <cuda_runtime.h>
#include <cuda_bf16.h>
#include <cuda_fp16.h>
#include <cstdint>
#include <cstddef>

// ===========================================================================
// RelativeAttention on sm_100 (plain target: legacy mma.sync / HMMA).
// R9: SIM reduced to 2 fp16 GEMMs (Qhi/Qlo fp16 x K fp16).
//
//   1) split x, anchors -> bf16 hi/lo; transpose+split Wq, Wk; values -> Vt fp16
//   2) Qf = x @ Wq, Kf = anchors @ Wk    (3-term bf16 mma, fp32 store)
//   3) l2norm rows: Q -> fp16 hi/lo, K -> fp16
//   4) zero den
//   5) SIM (2-term fp16): quant->exp -> E fp16 + rowsum atomics
//   6) OUT (1-term fp16): O = E @ Vt^T -> scale 1/den -> fp32 out
// ===========================================================================

// ------------------------- device scratch ----------------------------------
__device__ float g_Qf[16384 * 512];
__device__ float g_Kf[4096 * 512];
__device__ float g_den[16384];
__device__ __nv_bfloat16 g_xhi[16384 * 512];
__device__ __nv_bfloat16 g_xlo[16384 * 512];
__device__ __nv_bfloat16 g_ahi[4096 * 512];
__device__ __nv_bfloat16 g_alo[4096 * 512];
__device__ __nv_bfloat16 g_Wqthi[512 * 512];
__device__ __nv_bfloat16 g_Wqtlo[512 * 512];
__device__ __nv_bfloat16 g_Wkthi[512 * 512];
__device__ __nv_bfloat16 g_Wktlo[512 * 512];
__device__ __half g_Qhi[16384 * 512];
__device__ __half g_Qlo[16384 * 512];
__device__ __half g_Kh[4096 * 512];
__device__ __half g_E[(size_t)16384 * 4096];
__device__ __half g_Vt[512 * 4096];

// ------------------------- helpers -----------------------------------------
__device__ __forceinline__ uint32_t s2u(const void* p) {
    uint32_t a;
    asm("{ .reg .u64 t; cvta.to.shared.u64 t, %1; cvt.u32.u64 %0, t; }"
        : "=r"(a) : "l"(p));
    return a;
}

__device__ __forceinline__ void cp16(uint32_t dst, const void* src) {
    asm volatile("cp.async.cg.shared.global [%0], [%1], 16;" :: "r"(dst), "l"(src));
}
#define CP_COMMIT() asm volatile("cp.async.commit_group;" ::: "memory")
#define CP_WAIT1()  asm volatile("cp.async.wait_group 1;" ::: "memory")

__device__ __forceinline__ void ldsm4(uint32_t* r, uint32_t addr) {
    asm volatile("ldmatrix.sync.aligned.m8n8.x4.shared.b16 {%0,%1,%2,%3}, [%4];"
        : "=r"(r[0]), "=r"(r[1]), "=r"(r[2]), "=r"(r[3]) : "r"(addr));
}

__device__ __forceinline__ void mma_bf16(float* d, const uint32_t* a, const uint32_t* b) {
    asm volatile(
        "mma.sync.aligned.m16n8k16.row.col.f32.bf16.bf16.f32 "
        "{%0,%1,%2,%3}, {%4,%5,%6,%7}, {%8,%9}, {%0,%1,%2,%3};"
        : "+f"(d[0]), "+f"(d[1]), "+f"(d[2]), "+f"(d[3])
        : "r"(a[0]), "r"(a[1]), "r"(a[2]), "r"(a[3]), "r"(b[0]), "r"(b[1]));
}

__device__ __forceinline__ void mma_f16(float* d, const uint32_t* a, const uint32_t* b) {
    asm volatile(
        "mma.sync.aligned.m16n8k16.row.col.f32.f16.f16.f32 "
        "{%0,%1,%2,%3}, {%4,%5,%6,%7}, {%8,%9}, {%0,%1,%2,%3};"
        : "+f"(d[0]), "+f"(d[1]), "+f"(d[2]), "+f"(d[3])
        : "r"(a[0]), "r"(a[1]), "r"(a[2]), "r"(a[3]), "r"(b[0]), "r"(b[1]));
}

__device__ __forceinline__ uint32_t pack_bf2(float a, float b) {
    __nv_bfloat16 ha = __float2bfloat16(a), hb = __float2bfloat16(b);
    return (uint32_t)__bfloat16_as_ushort(ha) |
           ((uint32_t)__bfloat16_as_ushort(hb) << 16);
}
__device__ __forceinline__ uint32_t pack_h2(float a, float b) {
    __half2 h = __floats2half2_rn(a, b);
    return *(uint32_t*)&h;
}

// ------------------------- tiling constants ---------------------------------
// 128x128x32 block tile, 256 threads, 8 warps (4 M x 2 N), warp tile 32x64.
// smem rows: 64B data + 16B pad = 80B (5x16B, gcd(5,8)=1 -> LDSM conflict-free)
#define ROWB 80
#define TILEB (128 * ROWB)              // 10240 per tile
#define STAGE4 (4 * TILEB)              // proj: Ahi,Alo,Bhi,Blo
#define STAGE3T (3 * TILEB)             // sim:  Ahi,Alo,B
#define STAGE2T (2 * TILEB)             // out:  A,B
static constexpr int SMEM4 = 2 * STAGE4;    // 81920
static constexpr int SMEM3T = 2 * STAGE3T;  // 61440
static constexpr int SMEM2T = 2 * STAGE2T;  // 40960

// ------------------------- stage loaders ------------------------------------
__device__ __forceinline__ void load_stage4(
    uint32_t sbase, const __nv_bfloat16* Ahi, const __nv_bfloat16* Alo,
    const __nv_bfloat16* Bhi, const __nv_bfloat16* Blo,
    int bm0, int bn0, int K, int c, int tid)
{
    const __nv_bfloat16* gp[4] = { Ahi, Alo, Bhi, Blo };
    const int rb[4] = { bm0, bm0, bn0, bn0 };
    const size_t kb = (size_t)c * 32;
#pragma unroll
    for (int t = 0; t < 8; t++) {
        const int seg  = tid + t * 256;
        const int tile = seg >> 9;
        const int w    = seg & 511;
        const int row  = w >> 2;
        const int c16  = w & 3;
        const __nv_bfloat16* src = gp[tile] + (size_t)(rb[tile] + row) * K + kb + c16 * 8;
        cp16(sbase + tile * TILEB + row * ROWB + c16 * 16, src);
    }
}

__device__ __forceinline__ void load_stage3(
    uint32_t sbase, const __half* Ahi, const __half* Alo, const __half* B,
    int bm0, int bn0, int K, int c, int tid)
{
    const __half* gp[3] = { Ahi, Alo, B };
    const int rb[3] = { bm0, bm0, bn0 };
    const size_t kb = (size_t)c * 32;
#pragma unroll
    for (int t = 0; t < 6; t++) {
        const int seg  = tid + t * 256;
        const int tile = seg >> 9;
        const int w    = seg & 511;
        const int row  = w >> 2;
        const int c16  = w & 3;
        const __half* src = gp[tile] + (size_t)(rb[tile] + row) * K + kb + c16 * 8;
        cp16(sbase + tile * TILEB + row * ROWB + c16 * 16, src);
    }
}

__device__ __forceinline__ void load_stage2(
    uint32_t sbase, const __half* A, const __half* B,
    int bm0, int bn0, int K, int c, int tid)
{
    const __half* gp[2] = { A, B };
    const int rb[2] = { bm0, bn0 };
    const size_t kb = (size_t)c * 32;
#pragma unroll
    for (int t = 0; t < 4; t++) {
        const int seg  = tid + t * 256;
        const int tile = seg >> 9;
        const int w    = seg & 511;
        const int row  = w >> 2;
        const int c16  = w & 3;
        const __half* src = gp[tile] + (size_t)(rb[tile] + row) * K + kb + c16 * 8;
        cp16(sbase + tile * TILEB + row * ROWB + c16 * 16, src);
    }
}

// ------------------------- 3-term bf16 projection GEMM ----------------------
// Cf[M,N] = Ahi@Bhi^T + Ahi@Blo^T + Alo@Bhi^T  (fp32 store)
__global__ __launch_bounds__(256, 2)
void proj3_kernel(const __nv_bfloat16* __restrict__ Ahi,
                  const __nv_bfloat16* __restrict__ Alo,
                  const __nv_bfloat16* __restrict__ Bhi,
                  const __nv_bfloat16* __restrict__ Blo,
                  int K, int ldC,
                  float* __restrict__ Cf)
{
    extern __shared__ char sm[];
    const uint32_t sb = s2u(sm);
    const int tid  = threadIdx.x;
    const int wid  = tid >> 5;
    const int lane = tid & 31;
    const int wm   = wid >> 1;
    const int wn   = wid & 1;
    const int g    = lane >> 2;
    const int tg   = lane & 3;
    const int bm0  = blockIdx.y * 128;
    const int bn0  = blockIdx.x * 128;

    const int grp  = lane >> 3;
    const int lrow = lane & 7;
    const uint32_t a_off = (uint32_t)((wm * 32 + lrow + ((grp & 1) << 3)) * ROWB
                                      + ((grp >> 1) << 4));
    const uint32_t b_off = (uint32_t)((wn * 64 + lrow + ((grp >> 1) << 3)) * ROWB
                                      + ((grp & 1) << 4));

    float acc[2][8][4];
#pragma unroll
    for (int mt = 0; mt < 2; mt++)
#pragma unroll
        for (int nt = 0; nt < 8; nt++)
#pragma unroll
            for (int j = 0; j < 4; j++) acc[mt][nt][j] = 0.f;

    const int nch = K >> 5;
    load_stage4(sb,          Ahi, Alo, Bhi, Blo, bm0, bn0, K, 0, tid);
    CP_COMMIT();
    load_stage4(sb + STAGE4, Ahi, Alo, Bhi, Blo, bm0, bn0, K, 1, tid);
    CP_COMMIT();

    for (int c = 0; c < nch; c++) {
        CP_WAIT1();
        __syncthreads();
        const uint32_t st = sb + (c & 1) * STAGE4;

#pragma unroll
        for (int ks = 0; ks < 2; ks++) {
            const uint32_t kk = ks * 32;
            uint32_t ah[2][4], al[2][4], bh[4][4], bl[4][4];
#pragma unroll
            for (int mt = 0; mt < 2; mt++) {
                ldsm4(ah[mt], st + a_off + mt * (16 * ROWB) + kk);
                ldsm4(al[mt], st + TILEB + a_off + mt * (16 * ROWB) + kk);
            }
#pragma unroll
            for (int np = 0; np < 4; np++) {
                ldsm4(bh[np], st + 2 * TILEB + b_off + np * (16 * ROWB) + kk);
                ldsm4(bl[np], st + 3 * TILEB + b_off + np * (16 * ROWB) + kk);
            }
#pragma unroll
            for (int np = 0; np < 4; np++)
#pragma unroll
                for (int sub = 0; sub < 2; sub++)
#pragma unroll
                    for (int mt = 0; mt < 2; mt++) {
                        mma_bf16(acc[mt][np * 2 + sub], ah[mt], &bh[np][2 * sub]);
                        mma_bf16(acc[mt][np * 2 + sub], ah[mt], &bl[np][2 * sub]);
                        mma_bf16(acc[mt][np * 2 + sub], al[mt], &bh[np][2 * sub]);
                    }
        }
        __syncthreads();
        if (c + 2 < nch)
            load_stage4(sb + (c & 1) * STAGE4, Ahi, Alo, Bhi, Blo, bm0, bn0, K, c + 2, tid);
        CP_COMMIT();
    }

#pragma unroll
    for (int mt = 0; mt < 2; mt++) {
        const int rh = bm0 + wm * 32 + mt * 16 + g;
        const int rl = rh + 8;
#pragma unroll
        for (int nt = 0; nt < 8; nt++) {
            const int col = bn0 + wn * 64 + nt * 8 + tg * 2;
            *(float2*)(Cf + (size_t)rh * ldC + col) =
                make_float2(acc[mt][nt][0], acc[mt][nt][1]);
            *(float2*)(Cf + (size_t)rl * ldC + col) =
                make_float2(acc[mt][nt][2], acc[mt][nt][3]);
        }
    }
}

// ------------------------- 2-term fp16 SIM kernel ---------------------------
// S = Ahi@B^T + Alo@B^T; epilogue: quant->exp -> E fp16 + rowsum atomics.
__global__ __launch_bounds__(256, 2)
void sim2_kernel(const __half* __restrict__ Ahi,
                 const __half* __restrict__ Alo,
                 const __half* __restrict__ Bk,
                 int K, int ldC,
                 float* __restrict__ den,
                 __half* __restrict__ E)
{
    extern __shared__ char sm[];
    const uint32_t sb = s2u(sm);
    const int tid  = threadIdx.x;
    const int wid  = tid >> 5;
    const int lane = tid & 31;
    const int wm   = wid >> 1;
    const int wn   = wid & 1;
    const int g    = lane >> 2;
    const int tg   = lane & 3;
    const int bm0  = blockIdx.y * 128;
    const int bn0  = blockIdx.x * 128;

    const int grp  = lane >> 3;
    const int lrow = lane & 7;
    const uint32_t a_off = (uint32_t)((wm * 32 + lrow + ((grp & 1) << 3)) * ROWB
                                      + ((grp >> 1) << 4));
    const uint32_t b_off = (uint32_t)((wn * 64 + lrow + ((grp >> 1) << 3)) * ROWB
                                      + ((grp & 1) << 4));

    float acc[2][8][4];
#pragma unroll
    for (int mt = 0; mt < 2; mt++)
#pragma unroll
        for (int nt = 0; nt < 8; nt++)
#pragma unroll
            for (int j = 0; j < 4; j++) acc[mt][nt][j] = 0.f;

    const int nch = K >> 5;
    load_stage3(sb,           Ahi, Alo, Bk, bm0, bn0, K, 0, tid);
    CP_COMMIT();
    load_stage3(sb + STAGE3T, Ahi, Alo, Bk, bm0, bn0, K, 1, tid);
    CP_COMMIT();

    for (int c = 0; c < nch; c++) {
        CP_WAIT1();
        __syncthreads();
        const uint32_t st = sb + (c & 1) * STAGE3T;

#pragma unroll
        for (int ks = 0; ks < 2; ks++) {
            const uint32_t kk = ks * 32;
            uint32_t ah[2][4], al[2][4], bh[4][4];
#pragma unroll
            for (int mt = 0; mt < 2; mt++) {
                ldsm4(ah[mt], st + a_off + mt * (16 * ROWB) + kk);
                ldsm4(al[mt], st + TILEB + a_off + mt * (16 * ROWB) + kk);
            }
#pragma unroll
            for (int np = 0; np < 4; np++)
                ldsm4(bh[np], st + 2 * TILEB + b_off + np * (16 * ROWB) + kk);
#pragma unroll
            for (int np = 0; np < 4; np++)
#pragma unroll
                for (int sub = 0; sub < 2; sub++)
#pragma unroll
                    for (int mt = 0; mt < 2; mt++)
                        mma_f16(acc[mt][np * 2 + sub], ah[mt], &bh[np][2 * sub]);
#pragma unroll
            for (int np = 0; np < 4; np++)
#pragma unroll
                for (int sub = 0; sub < 2; sub++)
#pragma unroll
                    for (int mt = 0; mt < 2; mt++)
                        mma_f16(acc[mt][np * 2 + sub], al[mt], &bh[np][2 * sub]);
        }
        __syncthreads();
        if (c + 2 < nch)
            load_stage3(sb + (c & 1) * STAGE3T, Ahi, Alo, Bk, bm0, bn0, K, c + 2, tid);
        CP_COMMIT();
    }

    // epilogue: quantize -> exp -> E fp16 + rowsum
    float rs[2][2] = { {0.f, 0.f}, {0.f, 0.f} };
#pragma unroll
    for (int mt = 0; mt < 2; mt++) {
        const int rh = bm0 + wm * 32 + mt * 16 + g;
        const int rl = rh + 8;
#pragma unroll
        for (int nt = 0; nt < 8; nt++) {
            const int col = bn0 + wn * 64 + nt * 8 + tg * 2;
            float e0 = __expf(rintf(acc[mt][nt][0] / 0.05f) * 0.05f);
            float e1 = __expf(rintf(acc[mt][nt][1] / 0.05f) * 0.05f);
            float e2 = __expf(rintf(acc[mt][nt][2] / 0.05f) * 0.05f);
            float e3 = __expf(rintf(acc[mt][nt][3] / 0.05f) * 0.05f);
            rs[mt][0] += e0 + e1;
            rs[mt][1] += e2 + e3;
            *(uint32_t*)(E + (size_t)rh * ldC + col) = pack_h2(e0, e1);
            *(uint32_t*)(E + (size_t)rl * ldC + col) = pack_h2(e2, e3);
        }
    }
#pragma unroll
    for (int mt = 0; mt < 2; mt++)
#pragma unroll
        for (int hl = 0; hl < 2; hl++) {
            float v = rs[mt][hl];
            v += __shfl_xor_sync(0xffffffffu, v, 1);
            v += __shfl_xor_sync(0xffffffffu, v, 2);
            if (tg == 0)
                atomicAdd(&den[bm0 + wm * 32 + mt * 16 + g + hl * 8], v);
        }
}

// ------------------------- 1-term fp16 OUT kernel ---------------------------
__global__ __launch_bounds__(256, 2)
void out1_kernel(const __half* __restrict__ E,
                 const __half* __restrict__ Vt,
                 int K, int ldC,
                 const float* __restrict__ den,
                 float* __restrict__ Cf)
{
    extern __shared__ char sm[];
    const uint32_t sb = s2u(sm);
    const int tid  = threadIdx.x;
    const int wid  = tid >> 5;
    const int lane = tid & 31;
    const int wm   = wid >> 1;
    const int wn   = wid & 1;
    const int g    = lane >> 2;
    const int tg   = lane & 3;
    const int bm0  = blockIdx.y * 128;
    const int bn0  = blockIdx.x * 128;

    const int grp  = lane >> 3;
    const int lrow = lane & 7;
    const uint32_t a_off = (uint32_t)((wm * 32 + lrow + ((grp & 1) << 3)) * ROWB
                                      + ((grp >> 1) << 4));
    const uint32_t b_off = (uint32_t)((wn * 64 + lrow + ((grp >> 1) << 3)) * ROWB
                                      + ((grp & 1) << 4));

    float acc[2][8][4];
#pragma unroll
    for (int mt = 0; mt < 2; mt++)
#pragma unroll
        for (int nt = 0; nt < 8; nt++)
#pragma unroll
            for (int j = 0; j < 4; j++) acc[mt][nt][j] = 0.f;

    const int nch = K >> 5;
    load_stage2(sb,           E, Vt, bm0, bn0, K, 0, tid);
    CP_COMMIT();
    load_stage2(sb + STAGE2T, E, Vt, bm0, bn0, K, 1, tid);
    CP_COMMIT();

    for (int c = 0; c < nch; c++) {
        CP_WAIT1();
        __syncthreads();
        const uint32_t st = sb + (c & 1) * STAGE2T;

#pragma unroll
        for (int ks = 0; ks < 2; ks++) {
            const uint32_t kk = ks * 32;
            uint32_t ah[2][4], bh[4][4];
#pragma unroll
            for (int mt = 0; mt < 2; mt++)
                ldsm4(ah[mt], st + a_off + mt * (16 * ROWB) + kk);
#pragma unroll
            for (int np = 0; np < 4; np++)
                ldsm4(bh[np], st + TILEB + b_off + np * (16 * ROWB) + kk);
#pragma unroll
            for (int np = 0; np < 4; np++)
#pragma unroll
                for (int sub = 0; sub < 2; sub++)
#pragma unroll
                    for (int mt = 0; mt < 2; mt++)
                        mma_f16(acc[mt][np * 2 + sub], ah[mt], &bh[np][2 * sub]);
        }
        __syncthreads();
        if (c + 2 < nch)
            load_stage2(sb + (c & 1) * STAGE2T, E, Vt, bm0, bn0, K, c + 2, tid);
        CP_COMMIT();
    }

#pragma unroll
    for (int mt = 0; mt < 2; mt++) {
        const int rh = bm0 + wm * 32 + mt * 16 + g;
        const int rl = rh + 8;
        const float sh = 1.0f / den[rh];
        const float sl = 1.0f / den[rl];
#pragma unroll
        for (int nt = 0; nt < 8; nt++) {
            const int col = bn0 + wn * 64 + nt * 8 + tg * 2;
            *(float2*)(Cf + (size_t)rh * ldC + col) =
                make_float2(acc[mt][nt][0] * sh, acc[mt][nt][1] * sh);
            *(float2*)(Cf + (size_t)rl * ldC + col) =
                make_float2(acc[mt][nt][2] * sl, acc[mt][nt][3] * sl);
        }
    }
}

// ------------------------- split fp32 -> bf16 hi/lo -------------------------
__global__ void split_kernel(const float* __restrict__ s,
                             __nv_bfloat16* __restrict__ hi,
                             __nv_bfloat16* __restrict__ lo, int n4)
{
    const int i = blockIdx.x * blockDim.x + threadIdx.x;
    if (i >= n4) return;
    float4 v = ((const float4*)s)[i];
    const float f[4] = { v.x, v.y, v.z, v.w };
    uint32_t hp[2], lp[2];
#pragma unroll
    for (int j = 0; j < 2; j++) {
        __nv_bfloat16 h0 = __float2bfloat16(f[2 * j]);
        __nv_bfloat16 h1 = __float2bfloat16(f[2 * j + 1]);
        hp[j] = (uint32_t)__bfloat16_as_ushort(h0) |
                ((uint32_t)__bfloat16_as_ushort(h1) << 16);
        lp[j] = pack_bf2(f[2 * j]     - __bfloat162float(h0),
                         f[2 * j + 1] - __bfloat162float(h1));
    }
    *(uint2*)(hi + (size_t)i * 4) = make_uint2(hp[0], hp[1]);
    *(uint2*)(lo + (size_t)i * 4) = make_uint2(lp[0], lp[1]);
}

// ----------------- transpose + split: src[R,C] -> out[C,R] bf16 hi/lo -------
__global__ void trans_split_kernel(const float* __restrict__ src,
                                   __nv_bfloat16* __restrict__ hi,
                                   __nv_bfloat16* __restrict__ lo,
                                   int R, int C)
{
    __shared__ float t[32][33];
    const int c0 = blockIdx.x * 32, r0 = blockIdx.y * 32;
    const int tx = threadIdx.x, ty = threadIdx.y;   // 32 x 8
#pragma unroll
    for (int j = 0; j < 32; j += 8)
        t[ty + j][tx] = src[(size_t)(r0 + ty + j) * C + c0 + tx];
    __syncthreads();
#pragma unroll
    for (int j = 0; j < 32; j += 8) {
        const float v = t[tx][ty + j];
        __nv_bfloat16 h = __float2bfloat16(v);
        const size_t o = (size_t)(c0 + ty + j) * R + r0 + tx;
        hi[o] = h;
        lo[o] = __float2bfloat16(v - __bfloat162float(h));
    }
}

// ----------------- transpose: src[R,C] fp32 -> out[C,R] fp16 ----------------
__global__ void trans_half_kernel(const float* __restrict__ src,
                                  __half* __restrict__ dst,
                                  int R, int C)
{
    __shared__ float t[32][33];
    const int c0 = blockIdx.x * 32, r0 = blockIdx.y * 32;
    const int tx = threadIdx.x, ty = threadIdx.y;   // 32 x 8
#pragma unroll
    for (int j = 0; j < 32; j += 8)
        t[ty + j][tx] = src[(size_t)(r0 + ty + j) * C + c0 + tx];
    __syncthreads();
#pragma unroll
    for (int j = 0; j < 32; j += 8)
        dst[(size_t)(c0 + ty + j) * R + r0 + tx] = __float2half_rn(t[tx][ty + j]);
}

// ------------------------- l2 normalize variants ----------------------------
// Q: fp16 hi + fp16 lo (residual); K: single fp16.
__global__ void l2norm_split_h_kernel(const float* __restrict__ P,
                                      __half* __restrict__ hi,
                                      __half* __restrict__ lo)
{
    const int r = blockIdx.x;
    const int t = threadIdx.x;  // 128 threads x float4 (H=512)
    const float4 v = ((const float4*)(P + (size_t)r * 512))[t];
    float ss = v.x * v.x + v.y * v.y + v.z * v.z + v.w * v.w;
#pragma unroll
    for (int m = 16; m; m >>= 1) ss += __shfl_xor_sync(0xffffffffu, ss, m);
    __shared__ float ws[4];
    if ((t & 31) == 0) ws[t >> 5] = ss;
    __syncthreads();
    const float d = fmaxf(sqrtf(ws[0] + ws[1] + ws[2] + ws[3]), 1e-12f);
    const float f[4] = { v.x / d, v.y / d, v.z / d, v.w / d };
    uint32_t hp[2], lp[2];
#pragma unroll
    for (int j = 0; j < 2; j++) {
        const float a = f[2 * j], b = f[2 * j + 1];
        __half h0 = __float2half_rn(a), h1 = __float2half_rn(b);
        __half2 hh; hh.x = h0; hh.y = h1;
        hp[j] = *(uint32_t*)&hh;
        lp[j] = pack_h2(a - __half2float(h0), b - __half2float(h1));
    }
    const size_t off = (size_t)r * 512 + t * 4;
    *(uint2*)(hi + off) = make_uint2(hp[0], hp[1]);
    *(uint2*)(lo + off) = make_uint2(lp[0], lp[1]);
}

__global__ void l2norm_h_kernel(const float* __restrict__ P,
                                __half* __restrict__ dst)
{
    const int r = blockIdx.x;
    const int t = threadIdx.x;
    const float4 v = ((const float4*)(P + (size_t)r * 512))[t];
    float ss = v.x * v.x + v.y * v.y + v.z * v.z + v.w * v.w;
#pragma unroll
    for (int m = 16; m; m >>= 1) ss += __shfl_xor_sync(0xffffffffu, ss, m);
    __shared__ float ws[4];
    if ((t & 31) == 0) ws[t >> 5] = ss;
    __syncthreads();
    const float d = fmaxf(sqrtf(ws[0] + ws[1] + ws[2] + ws[3]), 1e-12f);
    uint32_t hp[2];
    hp[0] = pack_h2(v.x / d, v.y / d);
    hp[1] = pack_h2(v.z / d, v.w / d);
    *(uint2*)(dst + (size_t)r * 512 + t * 4) = make_uint2(hp[0], hp[1]);
}

__global__ void zero_kernel(float* __restrict__ p, int n)
{
    const int i = blockIdx.x * blockDim.x + threadIdx.x;
    if (i < n) p[i] = 0.f;
}

// ------------------------- launch -------------------------------------------
extern "C" void kernel_launch(void* const* d_in, const int* in_sizes, int n_in,
                              void* d_out, int out_size)
{
    const float* x       = (const float*)d_in[0];
    const float* anchors = (const float*)d_in[1];
    const float* Wq      = (const float*)d_in[2];
    const float* Wk      = (const float*)d_in[3];
    const float* values  = (const float*)d_in[4];
    float* out = (float*)d_out;

    const int D = 512, H = 512;
    const int B = in_sizes[0] / D;   // 16384
    const int A = in_sizes[1] / D;   // 4096

    float *Qf, *Kf, *dn;
    __nv_bfloat16 *xhi, *xlo, *ahi, *alo, *Wqthi, *Wqtlo, *Wkthi, *Wktlo;
    __half *Qhi, *Qlo, *Kh, *E, *Vt;
    cudaGetSymbolAddress((void**)&Qf,    g_Qf);
    cudaGetSymbolAddress((void**)&Kf,    g_Kf);
    cudaGetSymbolAddress((void**)&dn,    g_den);
    cudaGetSymbolAddress((void**)&xhi,   g_xhi);
    cudaGetSymbolAddress((void**)&xlo,   g_xlo);
    cudaGetSymbolAddress((void**)&ahi,   g_ahi);
    cudaGetSymbolAddress((void**)&alo,   g_alo);
    cudaGetSymbolAddress((void**)&Wqthi, g_Wqthi);
    cudaGetSymbolAddress((void**)&Wqtlo, g_Wqtlo);
    cudaGetSymbolAddress((void**)&Wkthi, g_Wkthi);
    cudaGetSymbolAddress((void**)&Wktlo, g_Wktlo);
    cudaGetSymbolAddress((void**)&Qhi,   g_Qhi);
    cudaGetSymbolAddress((void**)&Qlo,   g_Qlo);
    cudaGetSymbolAddress((void**)&Kh,    g_Kh);
    cudaGetSymbolAddress((void**)&E,     g_E);
    cudaGetSymbolAddress((void**)&Vt,    g_Vt);

    cudaFuncSetAttribute(proj3_kernel,
                         cudaFuncAttributeMaxDynamicSharedMemorySize, SMEM4);
    cudaFuncSetAttribute(sim2_kernel,
                         cudaFuncAttributeMaxDynamicSharedMemorySize, SMEM3T);
    cudaFuncSetAttribute(out1_kernel,
                         cudaFuncAttributeMaxDynamicSharedMemorySize, SMEM2T);

    // 1) splits / transposes
    split_kernel<<<(B * D / 4 + 255) / 256, 256>>>(x, xhi, xlo, B * D / 4);
    split_kernel<<<(A * D / 4 + 255) / 256, 256>>>(anchors, ahi, alo, A * D / 4);
    trans_split_kernel<<<dim3(H / 32, D / 32), dim3(32, 8)>>>(Wq, Wqthi, Wqtlo, D, H);
    trans_split_kernel<<<dim3(H / 32, D / 32), dim3(32, 8)>>>(Wk, Wkthi, Wktlo, D, H);
    trans_half_kernel<<<dim3(H / 32, A / 32), dim3(32, 8)>>>(values, Vt, A, H);

    // 2) projections (3-term bf16 mma, fp32 store)
    proj3_kernel<<<dim3(H / 128, B / 128), 256, SMEM4>>>(
        xhi, xlo, Wqthi, Wqtlo, D, H, Qf);
    proj3_kernel<<<dim3(H / 128, A / 128), 256, SMEM4>>>(
        ahi, alo, Wkthi, Wktlo, D, H, Kf);

    // 3) l2 normalize: Q -> fp16 hi/lo, K -> fp16
    l2norm_split_h_kernel<<<B, 128>>>(Qf, Qhi, Qlo);
    l2norm_h_kernel<<<A, 128>>>(Kf, Kh);

    // 4) zero den
    zero_kernel<<<(B + 255) / 256, 256>>>(dn, B);

    // 5) SIM: E = exp(quant(Qn @ Kn^T)) fp16, den = rowsum (2-term fp16)
    sim2_kernel<<<dim3(A / 128, B / 128), 256, SMEM3T>>>(
        Qhi, Qlo, Kh, H, A, dn, E);

    // 6) OUT: out = (E @ V) / den  (1-term fp16)
    out1_kernel<<<dim3(H / 128, B / 128), 256, SMEM2T>>>(
        E, Vt, A, H, dn, out);
}